// round 1
// baseline (speedup 1.0000x reference)
#include <cuda_runtime.h>
#include <math.h>

#define T_TYPES 11
#define NUM_TX  131072
#define N_ENT   131072
#define NE      262144
#define H       128
#define TXF     394
#define LN_EPS  1e-5f
#define INV_SQRT_D 0.08838834764831845f   // 1/sqrt(128)

// ---------------- scratch (device globals; no cudaMalloc allowed) ----------
__device__ float g_q  [(size_t)N_ENT * H];
__device__ float g_k  [(size_t)N_ENT * H];
__device__ float g_v  [(size_t)N_ENT * H];
__device__ float g_hr [(size_t)N_ENT * H];   // root skip (x@Ws+bs), then LN output h
__device__ float g_hw [(size_t)N_ENT * H];   // h @ W1_t
__device__ float g_msg[(size_t)N_ENT * H];   // attention aggregation
__device__ float g_e  [NE];                  // edge scores -> exp values
__device__ float g_m  [N_ENT];               // segment max
__device__ float g_den[N_ENT];               // segment sum of exp
__device__ float g_h1 [(size_t)NUM_TX * H];  // pre-activation of layer-1 accumulator

// float atomic max via int/uint ordering trick
__device__ __forceinline__ void atomicMaxF(float* addr, float val) {
    if (val >= 0.0f) atomicMax((int*)addr, __float_as_int(val));
    else             atomicMin((unsigned int*)addr, (unsigned int)__float_as_int(val));
}

// ---------------- h1 init: b1 + tx_x @ W1[0:394, :] ------------------------
__global__ void k_init_h1(const float* __restrict__ tx,
                          const float* __restrict__ W1,
                          const float* __restrict__ b1) {
    __shared__ float xs[TXF];
    const int row = blockIdx.x;
    const int tid = threadIdx.x;           // 128 threads
    const float* trow = tx + (size_t)row * TXF;
    for (int i = tid; i < TXF; i += 128) xs[i] = trow[i];
    __syncthreads();
    float acc = b1[tid];
    #pragma unroll 2
    for (int k = 0; k < TXF; k++) acc = fmaf(xs[k], W1[k * H + tid], acc);
    g_h1[(size_t)row * H + tid] = acc;
}

// ---------------- per-type reset --------------------------------------------
__global__ void k_reset() {
    const int i = blockIdx.x * blockDim.x + threadIdx.x;
    if (i < N_ENT * H) g_msg[i] = 0.0f;
    if (i < N_ENT) { g_m[i] = -INFINITY; g_den[i] = 0.0f; }
}

// ---------------- gather + 4 fused GEMMs: q,k,v,root ------------------------
// block = 128 threads handles 8 entity rows, each thread owns one output col.
__global__ void k_qkvs(const float* __restrict__ emb, const int* __restrict__ idx,
                       const float* __restrict__ Wq, const float* __restrict__ bq,
                       const float* __restrict__ Wk, const float* __restrict__ bk,
                       const float* __restrict__ Wv, const float* __restrict__ bv,
                       const float* __restrict__ Ws, const float* __restrict__ bs) {
    __shared__ float xs[8][H];
    const int tid = threadIdx.x;
    const int rb  = blockIdx.x * 8;
    #pragma unroll
    for (int r = 0; r < 8; r++) {
        const int e = idx[rb + r];
        xs[r][tid] = emb[(size_t)e * H + tid];
    }
    __syncthreads();

    float aq[8] = {}, ak[8] = {}, av[8] = {}, as_[8] = {};
    for (int k4 = 0; k4 < H; k4 += 4) {
        float xr[8][4];
        #pragma unroll
        for (int r = 0; r < 8; r++) {
            float4 xv = *(const float4*)&xs[r][k4];
            xr[r][0] = xv.x; xr[r][1] = xv.y; xr[r][2] = xv.z; xr[r][3] = xv.w;
        }
        #pragma unroll
        for (int kk = 0; kk < 4; kk++) {
            const int k = k4 + kk;
            const float wq = Wq[k * H + tid], wk = Wk[k * H + tid];
            const float wv = Wv[k * H + tid], ws = Ws[k * H + tid];
            #pragma unroll
            for (int r = 0; r < 8; r++) {
                const float xv = xr[r][kk];
                aq[r]  = fmaf(xv, wq, aq[r]);
                ak[r]  = fmaf(xv, wk, ak[r]);
                av[r]  = fmaf(xv, wv, av[r]);
                as_[r] = fmaf(xv, ws, as_[r]);
            }
        }
    }
    const float biq = bq[tid], bik = bk[tid], biv = bv[tid], bis = bs[tid];
    #pragma unroll
    for (int r = 0; r < 8; r++) {
        const size_t o = (size_t)(rb + r) * H + tid;
        g_q[o]  = aq[r] + biq;
        g_k[o]  = ak[r] + bik;
        g_v[o]  = av[r] + biv;
        g_hr[o] = as_[r] + bis;
    }
}

// ---------------- edge scores + segment max ---------------------------------
__global__ void k_score(const int* __restrict__ src, const int* __restrict__ dst) {
    const int gt = blockIdx.x * blockDim.x + threadIdx.x;
    const int e = gt >> 5, lane = gt & 31;
    if (e >= NE) return;
    const int s = src[e], d = dst[e];
    const float4 a = ((const float4*)(g_q + (size_t)d * H))[lane];
    const float4 b = ((const float4*)(g_k + (size_t)s * H))[lane];
    float acc = a.x * b.x + a.y * b.y + a.z * b.z + a.w * b.w;
    #pragma unroll
    for (int o = 16; o; o >>= 1) acc += __shfl_xor_sync(0xffffffffu, acc, o);
    if (lane == 0) {
        acc *= INV_SQRT_D;
        g_e[e] = acc;
        atomicMaxF(&g_m[d], acc);
    }
}

// ---------------- exp + segment denominator ---------------------------------
__global__ void k_exp(const int* __restrict__ dst) {
    const int e = blockIdx.x * blockDim.x + threadIdx.x;
    if (e >= NE) return;
    const int d = dst[e];
    const float v = expf(g_e[e] - g_m[d]);
    g_e[e] = v;
    atomicAdd(&g_den[d], v);
}

// ---------------- weighted message aggregation ------------------------------
__global__ void k_msg(const int* __restrict__ src, const int* __restrict__ dst) {
    const int gt = blockIdx.x * blockDim.x + threadIdx.x;
    const int e = gt >> 5, lane = gt & 31;
    if (e >= NE) return;
    const int s = src[e], d = dst[e];
    const float w = g_e[e] / g_den[d];
    const float4 vv = ((const float4*)(g_v + (size_t)s * H))[lane];
    float* b = g_msg + (size_t)d * H + lane * 4;
    atomicAdd(b + 0, w * vv.x);
    atomicAdd(b + 1, w * vv.y);
    atomicAdd(b + 2, w * vv.z);
    atomicAdd(b + 3, w * vv.w);
}

// ---------------- h = LN(msg + root) * g + b --------------------------------
__global__ void k_ln(const float* __restrict__ lns, const float* __restrict__ lnb) {
    const int row = blockIdx.x, tid = threadIdx.x;   // 128 threads
    const size_t o = (size_t)row * H + tid;
    const float hv = g_msg[o] + g_hr[o];
    float s = hv, s2 = hv * hv;
    #pragma unroll
    for (int off = 16; off; off >>= 1) {
        s  += __shfl_xor_sync(0xffffffffu, s,  off);
        s2 += __shfl_xor_sync(0xffffffffu, s2, off);
    }
    __shared__ float ss[4], ss2[4];
    const int w = tid >> 5;
    if ((tid & 31) == 0) { ss[w] = s; ss2[w] = s2; }
    __syncthreads();
    s  = ss[0]  + ss[1]  + ss[2]  + ss[3];
    s2 = ss2[0] + ss2[1] + ss2[2] + ss2[3];
    const float mu  = s * (1.0f / H);
    const float var = s2 * (1.0f / H) - mu * mu;
    g_hr[o] = (hv - mu) * rsqrtf(var + LN_EPS) * lns[tid] + lnb[tid];
}

// ---------------- hw = h @ W1_t (16 rows / block) ----------------------------
__global__ void k_hw(const float* __restrict__ W1t) {
    __shared__ float xs[16][H];
    const int tid = threadIdx.x;
    const int rb  = blockIdx.x * 16;
    #pragma unroll
    for (int r = 0; r < 16; r++) xs[r][tid] = g_hr[(size_t)(rb + r) * H + tid];
    __syncthreads();
    float acc[16] = {};
    for (int k4 = 0; k4 < H; k4 += 4) {
        float xr[16][4];
        #pragma unroll
        for (int r = 0; r < 16; r++) {
            float4 xv = *(const float4*)&xs[r][k4];
            xr[r][0] = xv.x; xr[r][1] = xv.y; xr[r][2] = xv.z; xr[r][3] = xv.w;
        }
        #pragma unroll
        for (int kk = 0; kk < 4; kk++) {
            const float w = W1t[(k4 + kk) * H + tid];
            #pragma unroll
            for (int r = 0; r < 16; r++) acc[r] = fmaf(xr[r][kk], w, acc[r]);
        }
    }
    #pragma unroll
    for (int r = 0; r < 16; r++) g_hw[(size_t)(rb + r) * H + tid] = acc[r];
}

// ---------------- scatter: h1[dst] += hw[src] --------------------------------
__global__ void k_scatter(const int* __restrict__ src, const int* __restrict__ dst) {
    const int gt = blockIdx.x * blockDim.x + threadIdx.x;
    const int e = gt >> 5, lane = gt & 31;
    if (e >= NE) return;
    const int s = src[e], d = dst[e];
    const float4 hv = ((const float4*)(g_hw + (size_t)s * H))[lane];
    float* b = g_h1 + (size_t)d * H + lane * 4;
    atomicAdd(b + 0, hv.x);
    atomicAdd(b + 1, hv.y);
    atomicAdd(b + 2, hv.z);
    atomicAdd(b + 3, hv.w);
}

// ---------------- tail MLP: relu -> W2(64) relu -> W3(1) --------------------
__global__ void k_mlp(const float* __restrict__ W2, const float* __restrict__ b2,
                      const float* __restrict__ W3, const float* __restrict__ b3,
                      float* __restrict__ out) {
    __shared__ float h1s[H];
    __shared__ float red[2];
    const int row = blockIdx.x, tid = threadIdx.x;   // 64 threads
    h1s[tid]      = fmaxf(g_h1[(size_t)row * H + tid],      0.0f);
    h1s[tid + 64] = fmaxf(g_h1[(size_t)row * H + tid + 64], 0.0f);
    __syncthreads();
    float acc = b2[tid];
    #pragma unroll 4
    for (int k = 0; k < H; k++) acc = fmaf(h1s[k], W2[k * 64 + tid], acc);
    float v = fmaxf(acc, 0.0f) * W3[tid];
    #pragma unroll
    for (int o = 16; o; o >>= 1) v += __shfl_xor_sync(0xffffffffu, v, o);
    if ((tid & 31) == 0) red[tid >> 5] = v;
    __syncthreads();
    if (tid == 0) out[row] = red[0] + red[1] + b3[0];
}

// ---------------- host launcher ---------------------------------------------
extern "C" void kernel_launch(void* const* d_in, const int* in_sizes, int n_in,
                              void* d_out, int out_size) {
    const float* tx_x = (const float*)d_in[0];
    const float* emb  = (const float*)d_in[1];
    const int*   eidx = (const int*)  d_in[2];
    const int*   esrc = (const int*)  d_in[3];
    const int*   edst = (const int*)  d_in[4];
    const float* Wq = (const float*)d_in[5],  *bq = (const float*)d_in[6];
    const float* Wk = (const float*)d_in[7],  *bk = (const float*)d_in[8];
    const float* Wv = (const float*)d_in[9],  *bv = (const float*)d_in[10];
    const float* Ws = (const float*)d_in[11], *bs = (const float*)d_in[12];
    const float* lns = (const float*)d_in[13], *lnb = (const float*)d_in[14];
    const float* W1 = (const float*)d_in[15], *b1 = (const float*)d_in[16];
    const float* W2 = (const float*)d_in[17], *b2 = (const float*)d_in[18];
    const float* W3 = (const float*)d_in[19], *b3 = (const float*)d_in[20];
    float* out = (float*)d_out;

    k_init_h1<<<NUM_TX, 128>>>(tx_x, W1, b1);

    const int edge_warp_blocks = (NE * 32 + 255) / 256;
    for (int t = 0; t < T_TYPES; t++) {
        const int*   src_t = esrc + (size_t)t * NE;
        const int*   dst_t = edst + (size_t)t * NE;
        k_reset  <<<(N_ENT * H + 255) / 256, 256>>>();
        k_qkvs   <<<N_ENT / 8, 128>>>(emb + (size_t)t * N_ENT * H,
                                      eidx + (size_t)t * N_ENT,
                                      Wq, bq, Wk, bk, Wv, bv, Ws, bs);
        k_score  <<<edge_warp_blocks, 256>>>(src_t, dst_t);
        k_exp    <<<(NE + 255) / 256, 256>>>(dst_t);
        k_msg    <<<edge_warp_blocks, 256>>>(src_t, dst_t);
        k_ln     <<<N_ENT, 128>>>(lns + t * H, lnb + t * H);
        k_hw     <<<N_ENT / 16, 128>>>(W1 + (size_t)(TXF + t * H) * H);
        k_scatter<<<edge_warp_blocks, 256>>>(src_t, dst_t);
    }

    k_mlp<<<NUM_TX, 64>>>(W2, b2, W3, b3, out);
}

// round 3
// speedup vs baseline: 1.3566x; 1.3566x over previous
#include <cuda_runtime.h>
#include <cuda_bf16.h>
#include <math.h>
#include <stdint.h>

#define T_TYPES 11
#define NUM_TX  131072
#define N_ENT   131072
#define NE      262144
#define H       128
#define TXF     394
#define LN_EPS  1e-5f
#define INV_SQRT_D 0.08838834764831845f   // 1/sqrt(128)

// bf16 tile strides (bytes): 128 bf16 = 256B + 16B pad -> conflict-free ldmatrix
#define SA 272
#define ATILE   34816     // 128 rows * 272B
#define ATILE2  69632     // 256 rows * 272B
#define BTILE   34816     // 128 n-rows * 272B

// ---------------- scratch (device globals; no cudaMalloc allowed) ----------
__device__ float g_q  [(size_t)N_ENT * H];
__device__ float g_k  [(size_t)N_ENT * H];
__device__ float g_v  [(size_t)N_ENT * H];
__device__ float g_hr [(size_t)N_ENT * H];   // root skip, then LN output h
__device__ float g_hw [(size_t)N_ENT * H];   // h @ W1_t
__device__ float g_msg[(size_t)N_ENT * H];   // attention aggregation
__device__ float g_e  [NE];                  // edge scores -> exp values
__device__ float g_m  [N_ENT];               // segment max
__device__ float g_den[N_ENT];               // segment sum of exp
__device__ float g_h1 [(size_t)NUM_TX * H];  // layer-1 pre-activation accumulator

// ================= helpers ===================================================
__device__ __forceinline__ uint32_t smem_u32(const void* p) {
    uint32_t a;
    asm("{ .reg .u64 t; cvta.to.shared.u64 t, %1; cvt.u32.u64 %0, t; }" : "=r"(a) : "l"(p));
    return a;
}
__device__ __forceinline__ void ldmx4(uint32_t* r, uint32_t addr) {
    asm volatile("ldmatrix.sync.aligned.m8n8.x4.shared.b16 {%0,%1,%2,%3}, [%4];"
        : "=r"(r[0]), "=r"(r[1]), "=r"(r[2]), "=r"(r[3]) : "r"(addr));
}
__device__ __forceinline__ void mma_bf16(float* c, const uint32_t* a, uint32_t b0, uint32_t b1) {
    asm volatile("mma.sync.aligned.m16n8k16.row.col.f32.bf16.bf16.f32 "
        "{%0,%1,%2,%3}, {%4,%5,%6,%7}, {%8,%9}, {%0,%1,%2,%3};"
        : "+f"(c[0]), "+f"(c[1]), "+f"(c[2]), "+f"(c[3])
        : "r"(a[0]), "r"(a[1]), "r"(a[2]), "r"(a[3]), "r"(b0), "r"(b1));
}
// pack two floats -> bf16x2 (lo in low half)
__device__ __forceinline__ uint32_t bfpack(float a, float b) {
    __nv_bfloat162 t = __floats2bfloat162_rn(a, b);
    return reinterpret_cast<uint32_t&>(t);
}
// split 4 floats into hi/lo bf16x2 pairs
__device__ __forceinline__ void split4(float4 v, uint32_t* hi, uint32_t* lo) {
    __nv_bfloat16 hx = __float2bfloat16(v.x), hy = __float2bfloat16(v.y);
    __nv_bfloat16 hz = __float2bfloat16(v.z), hw = __float2bfloat16(v.w);
    __nv_bfloat162 h01; h01.x = hx; h01.y = hy;
    __nv_bfloat162 h23; h23.x = hz; h23.y = hw;
    hi[0] = reinterpret_cast<uint32_t&>(h01);
    hi[1] = reinterpret_cast<uint32_t&>(h23);
    lo[0] = bfpack(v.x - __bfloat162float(hx), v.y - __bfloat162float(hy));
    lo[1] = bfpack(v.z - __bfloat162float(hz), v.w - __bfloat162float(hw));
}
__device__ __forceinline__ void atomicMaxF(float* addr, float val) {
    if (val >= 0.0f) atomicMax((int*)addr, __float_as_int(val));
    else             atomicMin((unsigned int*)addr, (unsigned int)__float_as_int(val));
}

// ================= h1 init: b1 + tx_x @ W1[0:394, :] ========================
__global__ void k_init_h1(const float* __restrict__ tx,
                          const float* __restrict__ W1,
                          const float* __restrict__ b1) {
    __shared__ float xs[TXF];
    const int row = blockIdx.x;
    const int tid = threadIdx.x;           // 128 threads
    const float* trow = tx + (size_t)row * TXF;
    for (int i = tid; i < TXF; i += 128) xs[i] = trow[i];
    __syncthreads();
    float acc = b1[tid];
    #pragma unroll 2
    for (int k = 0; k < TXF; k++) acc = fmaf(xs[k], W1[k * H + tid], acc);
    g_h1[(size_t)row * H + tid] = acc;
}

// ================= per-type reset ============================================
__global__ void k_reset() {
    const int i = blockIdx.x * blockDim.x + threadIdx.x;
    if (i < N_ENT * H) g_msg[i] = 0.0f;
    if (i < N_ENT) { g_m[i] = -INFINITY; g_den[i] = 0.0f; }
}

// ================= HMMA qkvs: gather + 2 GEMMs per y-half ===================
// grid (148, 2) persistent; y=0 -> (q,k), y=1 -> (v, root-skip). 512 threads.
// dyn smem: [Ah][Al][Bh0][Bl0][Bh1][Bl1][bias 2x128]
__global__ void __launch_bounds__(512, 1) k_qkvs_mma(
    const float* __restrict__ emb, const int* __restrict__ idx,
    const float* __restrict__ Wq, const float* __restrict__ bq,
    const float* __restrict__ Wk, const float* __restrict__ bk,
    const float* __restrict__ Wv, const float* __restrict__ bv,
    const float* __restrict__ Ws, const float* __restrict__ bs)
{
    extern __shared__ char dsraw[];
    const uint32_t raw  = smem_u32(dsraw);
    const uint32_t base = (raw + 1023u) & ~1023u;
    char* dsm = dsraw + (base - raw);

    const int tid = threadIdx.x, warp = tid >> 5, lane = tid & 31;

    const float *W0, *W1m, *bb0, *bb1;
    float *o0, *o1;
    if (blockIdx.y == 0) { W0 = Wq; bb0 = bq; W1m = Wk; bb1 = bk; o0 = g_q; o1 = g_k;  }
    else                 { W0 = Wv; bb0 = bv; W1m = Ws; bb1 = bs; o0 = g_v; o1 = g_hr; }

    char* Ahp = dsm;
    char* Alp = dsm + ATILE;
    char* Bp  = dsm + 2 * ATILE;            // [out][hi/lo] each BTILE
    float* bias = (float*)(dsm + 2 * ATILE + 4 * BTILE);

    // load + split weights: Bs[n][k] = W[k][n]
    for (int o = 0; o < 2; o++) {
        const float* W = o ? W1m : W0;
        char* bh = Bp + o * 2 * BTILE;
        char* bl = bh + BTILE;
        for (int i = tid; i < H * H; i += 512) {
            const int k = i >> 7, n = i & 127;
            const float w = W[i];
            const __nv_bfloat16 h = __float2bfloat16(w);
            *(__nv_bfloat16*)(bh + n * SA + k * 2) = h;
            *(__nv_bfloat16*)(bl + n * SA + k * 2) =
                __float2bfloat16(w - __bfloat162float(h));
        }
    }
    for (int i = tid; i < 256; i += 512) bias[i] = (i < 128) ? bb0[i] : bb1[i - 128];
    __syncthreads();

    const uint32_t AhA = smem_u32(Ahp), AlA = smem_u32(Alp);
    const int out = warp >> 3;            // 0/1
    const int rbw = ((warp >> 1) & 3) * 32;
    const int ch  = warp & 1;             // column half
    const uint32_t BhA = smem_u32(Bp + out * 2 * BTILE);
    const uint32_t BlA = BhA + BTILE;
    float* const outp = out ? o1 : o0;

    for (int tile = blockIdx.x; tile < N_ENT / 128; tile += gridDim.x) {
        const int rb = tile * 128;
        // ---- gather + split A: thread t -> row t>>2, quarter t&3 (8 float4)
        {
            const int r = tid >> 2, cq = tid & 3;
            const int e = __ldg(idx + rb + r);
            const float4* src = (const float4*)(emb + (size_t)e * H) + cq * 8;
            char* ah = Ahp + r * SA + cq * 64;
            char* al = Alp + r * SA + cq * 64;
            #pragma unroll
            for (int j = 0; j < 8; j++) {
                uint32_t hi[2], lo[2];
                split4(__ldg(src + j), hi, lo);
                *(uint32_t*)(ah + j * 8)     = hi[0];
                *(uint32_t*)(ah + j * 8 + 4) = hi[1];
                *(uint32_t*)(al + j * 8)     = lo[0];
                *(uint32_t*)(al + j * 8 + 4) = lo[1];
            }
        }
        __syncthreads();

        // ---- mma: warp computes 32x64 of output `out`
        float acc[2][8][4];
        #pragma unroll
        for (int mt = 0; mt < 2; mt++)
            #pragma unroll
            for (int nt = 0; nt < 8; nt++)
                #pragma unroll
                for (int q = 0; q < 4; q++) acc[mt][nt][q] = 0.0f;

        const uint32_t arow = rbw + (lane & 15);
        const uint32_t aqof = (lane >> 4) * 16;               // bytes: *8 cols *2B
        const uint32_t brow = ch * 64 + ((lane >> 4) * 8) + (lane & 7);
        const uint32_t bqof = ((lane >> 3) & 1) * 16;

        #pragma unroll
        for (int ks = 0; ks < 8; ks++) {
            const uint32_t kb = ks * 32;                      // k-step bytes (16 bf16)
            uint32_t ah[2][4], al[2][4], bf[4][4];
            #pragma unroll
            for (int mt = 0; mt < 2; mt++) {
                const uint32_t ao = (arow + mt * 16) * SA + kb + aqof;
                ldmx4(ah[mt], AhA + ao);
                ldmx4(al[mt], AlA + ao);
            }
            #pragma unroll
            for (int np = 0; np < 4; np++)
                ldmx4(bf[np], BhA + (brow + np * 16) * SA + kb + bqof);
            #pragma unroll
            for (int np = 0; np < 4; np++)
                #pragma unroll
                for (int sb = 0; sb < 2; sb++) {
                    const int nt = np * 2 + sb;
                    #pragma unroll
                    for (int mt = 0; mt < 2; mt++) {
                        mma_bf16(acc[mt][nt], ah[mt], bf[np][sb*2], bf[np][sb*2+1]);
                        mma_bf16(acc[mt][nt], al[mt], bf[np][sb*2], bf[np][sb*2+1]);
                    }
                }
            #pragma unroll
            for (int np = 0; np < 4; np++)
                ldmx4(bf[np], BlA + (brow + np * 16) * SA + kb + bqof);
            #pragma unroll
            for (int np = 0; np < 4; np++)
                #pragma unroll
                for (int sb = 0; sb < 2; sb++) {
                    const int nt = np * 2 + sb;
                    #pragma unroll
                    for (int mt = 0; mt < 2; mt++)
                        mma_bf16(acc[mt][nt], ah[mt], bf[np][sb*2], bf[np][sb*2+1]);
                }
        }

        // ---- epilogue: add bias, store float2
        #pragma unroll
        for (int mt = 0; mt < 2; mt++) {
            const int row0 = rb + rbw + mt * 16 + (lane >> 2);
            #pragma unroll
            for (int nt = 0; nt < 8; nt++) {
                const int col = ch * 64 + nt * 8 + (lane & 3) * 2;
                const float bv0 = bias[out * 128 + col], bv1 = bias[out * 128 + col + 1];
                float2 v0 = { acc[mt][nt][0] + bv0, acc[mt][nt][1] + bv1 };
                float2 v1 = { acc[mt][nt][2] + bv0, acc[mt][nt][3] + bv1 };
                *(float2*)(outp + (size_t)row0 * H + col)       = v0;
                *(float2*)(outp + (size_t)(row0 + 8) * H + col) = v1;
            }
        }
        __syncthreads();
    }
}

// ================= HMMA hw = h @ W1_t (256-row tiles) ========================
__global__ void __launch_bounds__(512, 1) k_hw_mma(const float* __restrict__ W1t)
{
    extern __shared__ char dsraw[];
    const uint32_t raw  = smem_u32(dsraw);
    const uint32_t base = (raw + 1023u) & ~1023u;
    char* dsm = dsraw + (base - raw);

    const int tid = threadIdx.x, warp = tid >> 5, lane = tid & 31;

    char* Ahp = dsm;
    char* Alp = dsm + ATILE2;
    char* Bhp = dsm + 2 * ATILE2;
    char* Blp = Bhp + BTILE;

    for (int i = tid; i < H * H; i += 512) {
        const int k = i >> 7, n = i & 127;
        const float w = W1t[i];
        const __nv_bfloat16 h = __float2bfloat16(w);
        *(__nv_bfloat16*)(Bhp + n * SA + k * 2) = h;
        *(__nv_bfloat16*)(Blp + n * SA + k * 2) = __float2bfloat16(w - __bfloat162float(h));
    }
    __syncthreads();

    const uint32_t AhA = smem_u32(Ahp), AlA = smem_u32(Alp);
    const uint32_t BhA = smem_u32(Bhp), BlA = smem_u32(Blp);
    const int rbw = (warp & 7) * 32;
    const int ch  = warp >> 3;

    for (int tile = blockIdx.x; tile < N_ENT / 256; tile += gridDim.x) {
        const int rb = tile * 256;
        // gather: thread t -> row t>>1, half t&1 (16 float4 each)
        {
            const int r = tid >> 1, hf = tid & 1;
            const float4* src = (const float4*)(g_hr + (size_t)(rb + r) * H) + hf * 16;
            char* ah = Ahp + r * SA + hf * 128;
            char* al = Alp + r * SA + hf * 128;
            #pragma unroll
            for (int j = 0; j < 16; j++) {
                uint32_t hi[2], lo[2];
                split4(__ldg(src + j), hi, lo);
                *(uint32_t*)(ah + j * 8)     = hi[0];
                *(uint32_t*)(ah + j * 8 + 4) = hi[1];
                *(uint32_t*)(al + j * 8)     = lo[0];
                *(uint32_t*)(al + j * 8 + 4) = lo[1];
            }
        }
        __syncthreads();

        float acc[2][8][4];
        #pragma unroll
        for (int mt = 0; mt < 2; mt++)
            #pragma unroll
            for (int nt = 0; nt < 8; nt++)
                #pragma unroll
                for (int q = 0; q < 4; q++) acc[mt][nt][q] = 0.0f;

        const uint32_t arow = rbw + (lane & 15);
        const uint32_t aqof = (lane >> 4) * 16;
        const uint32_t brow = ch * 64 + ((lane >> 4) * 8) + (lane & 7);
        const uint32_t bqof = ((lane >> 3) & 1) * 16;

        #pragma unroll
        for (int ks = 0; ks < 8; ks++) {
            const uint32_t kb = ks * 32;
            uint32_t ah[2][4], al[2][4], bf[4][4];
            #pragma unroll
            for (int mt = 0; mt < 2; mt++) {
                const uint32_t ao = (arow + mt * 16) * SA + kb + aqof;
                ldmx4(ah[mt], AhA + ao);
                ldmx4(al[mt], AlA + ao);
            }
            #pragma unroll
            for (int np = 0; np < 4; np++)
                ldmx4(bf[np], BhA + (brow + np * 16) * SA + kb + bqof);
            #pragma unroll
            for (int np = 0; np < 4; np++)
                #pragma unroll
                for (int sb = 0; sb < 2; sb++) {
                    const int nt = np * 2 + sb;
                    #pragma unroll
                    for (int mt = 0; mt < 2; mt++) {
                        mma_bf16(acc[mt][nt], ah[mt], bf[np][sb*2], bf[np][sb*2+1]);
                        mma_bf16(acc[mt][nt], al[mt], bf[np][sb*2], bf[np][sb*2+1]);
                    }
                }
            #pragma unroll
            for (int np = 0; np < 4; np++)
                ldmx4(bf[np], BlA + (brow + np * 16) * SA + kb + bqof);
            #pragma unroll
            for (int np = 0; np < 4; np++)
                #pragma unroll
                for (int sb = 0; sb < 2; sb++) {
                    const int nt = np * 2 + sb;
                    #pragma unroll
                    for (int mt = 0; mt < 2; mt++)
                        mma_bf16(acc[mt][nt], ah[mt], bf[np][sb*2], bf[np][sb*2+1]);
                }
        }

        #pragma unroll
        for (int mt = 0; mt < 2; mt++) {
            const int row0 = rb + rbw + mt * 16 + (lane >> 2);
            #pragma unroll
            for (int nt = 0; nt < 8; nt++) {
                const int col = ch * 64 + nt * 8 + (lane & 3) * 2;
                float2 v0 = { acc[mt][nt][0], acc[mt][nt][1] };
                float2 v1 = { acc[mt][nt][2], acc[mt][nt][3] };
                *(float2*)(g_hw + (size_t)row0 * H + col)       = v0;
                *(float2*)(g_hw + (size_t)(row0 + 8) * H + col) = v1;
            }
        }
        __syncthreads();
    }
}

// ================= edge scores + segment max =================================
__global__ void k_score(const int* __restrict__ src, const int* __restrict__ dst) {
    const int gt = blockIdx.x * blockDim.x + threadIdx.x;
    const int e = gt >> 5, lane = gt & 31;
    if (e >= NE) return;
    const int s = src[e], d = dst[e];
    const float4 a = ((const float4*)(g_q + (size_t)d * H))[lane];
    const float4 b = ((const float4*)(g_k + (size_t)s * H))[lane];
    float acc = a.x * b.x + a.y * b.y + a.z * b.z + a.w * b.w;
    #pragma unroll
    for (int o = 16; o; o >>= 1) acc += __shfl_xor_sync(0xffffffffu, acc, o);
    if (lane == 0) {
        acc *= INV_SQRT_D;
        g_e[e] = acc;
        atomicMaxF(&g_m[d], acc);
    }
}

// ================= exp + segment denominator =================================
__global__ void k_exp(const int* __restrict__ dst) {
    const int e = blockIdx.x * blockDim.x + threadIdx.x;
    if (e >= NE) return;
    const int d = dst[e];
    const float v = expf(g_e[e] - g_m[d]);
    g_e[e] = v;
    atomicAdd(&g_den[d], v);
}

// ================= weighted message aggregation ==============================
__global__ void k_msg(const int* __restrict__ src, const int* __restrict__ dst) {
    const int gt = blockIdx.x * blockDim.x + threadIdx.x;
    const int e = gt >> 5, lane = gt & 31;
    if (e >= NE) return;
    const int s = src[e], d = dst[e];
    const float w = g_e[e] / g_den[d];
    const float4 vv = ((const float4*)(g_v + (size_t)s * H))[lane];
    float* b = g_msg + (size_t)d * H + lane * 4;
    atomicAdd(b + 0, w * vv.x);
    atomicAdd(b + 1, w * vv.y);
    atomicAdd(b + 2, w * vv.z);
    atomicAdd(b + 3, w * vv.w);
}

// ================= h = LN(msg + root) * g + b ================================
__global__ void k_ln(const float* __restrict__ lns, const float* __restrict__ lnb) {
    const int row = blockIdx.x, tid = threadIdx.x;   // 128 threads
    const size_t o = (size_t)row * H + tid;
    const float hv = g_msg[o] + g_hr[o];
    float s = hv, s2 = hv * hv;
    #pragma unroll
    for (int off = 16; off; off >>= 1) {
        s  += __shfl_xor_sync(0xffffffffu, s,  off);
        s2 += __shfl_xor_sync(0xffffffffu, s2, off);
    }
    __shared__ float ss[4], ss2[4];
    const int w = tid >> 5;
    if ((tid & 31) == 0) { ss[w] = s; ss2[w] = s2; }
    __syncthreads();
    s  = ss[0]  + ss[1]  + ss[2]  + ss[3];
    s2 = ss2[0] + ss2[1] + ss2[2] + ss2[3];
    const float mu  = s * (1.0f / H);
    const float var = s2 * (1.0f / H) - mu * mu;
    g_hr[o] = (hv - mu) * rsqrtf(var + LN_EPS) * lns[tid] + lnb[tid];
}

// ================= scatter: h1[dst] += hw[src] ================================
__global__ void k_scatter(const int* __restrict__ src, const int* __restrict__ dst) {
    const int gt = blockIdx.x * blockDim.x + threadIdx.x;
    const int e = gt >> 5, lane = gt & 31;
    if (e >= NE) return;
    const int s = src[e], d = dst[e];
    const float4 hv = ((const float4*)(g_hw + (size_t)s * H))[lane];
    float* b = g_h1 + (size_t)d * H + lane * 4;
    atomicAdd(b + 0, hv.x);
    atomicAdd(b + 1, hv.y);
    atomicAdd(b + 2, hv.z);
    atomicAdd(b + 3, hv.w);
}

// ================= tail MLP: relu -> W2(64) relu -> W3(1) ====================
__global__ void k_mlp(const float* __restrict__ W2, const float* __restrict__ b2,
                      const float* __restrict__ W3, const float* __restrict__ b3,
                      float* __restrict__ out) {
    __shared__ float h1s[H];
    __shared__ float red[2];
    const int row = blockIdx.x, tid = threadIdx.x;   // 64 threads
    h1s[tid]      = fmaxf(g_h1[(size_t)row * H + tid],      0.0f);
    h1s[tid + 64] = fmaxf(g_h1[(size_t)row * H + tid + 64], 0.0f);
    __syncthreads();
    float acc = b2[tid];
    #pragma unroll 4
    for (int k = 0; k < H; k++) acc = fmaf(h1s[k], W2[k * 64 + tid], acc);
    float v = fmaxf(acc, 0.0f) * W3[tid];
    #pragma unroll
    for (int o = 16; o; o >>= 1) v += __shfl_xor_sync(0xffffffffu, v, o);
    if ((tid & 31) == 0) red[tid >> 5] = v;
    __syncthreads();
    if (tid == 0) out[row] = red[0] + red[1] + b3[0];
}

// ================= host launcher =============================================
extern "C" void kernel_launch(void* const* d_in, const int* in_sizes, int n_in,
                              void* d_out, int out_size) {
    const float* tx_x = (const float*)d_in[0];
    const float* emb  = (const float*)d_in[1];
    const int*   eidx = (const int*)  d_in[2];
    const int*   esrc = (const int*)  d_in[3];
    const int*   edst = (const int*)  d_in[4];
    const float* Wq = (const float*)d_in[5],  *bq = (const float*)d_in[6];
    const float* Wk = (const float*)d_in[7],  *bk = (const float*)d_in[8];
    const float* Wv = (const float*)d_in[9],  *bv = (const float*)d_in[10];
    const float* Ws = (const float*)d_in[11], *bs = (const float*)d_in[12];
    const float* lns = (const float*)d_in[13], *lnb = (const float*)d_in[14];
    const float* W1 = (const float*)d_in[15], *b1 = (const float*)d_in[16];
    const float* W2 = (const float*)d_in[17], *b2 = (const float*)d_in[18];
    const float* W3 = (const float*)d_in[19], *b3 = (const float*)d_in[20];
    float* out = (float*)d_out;

    const int QKVS_SMEM = 2 * ATILE + 4 * BTILE + 1024 + 1024;   // 211968
    const int HW_SMEM   = 2 * ATILE2 + 2 * BTILE + 1024;         // 209920
    cudaFuncSetAttribute(k_qkvs_mma, cudaFuncAttributeMaxDynamicSharedMemorySize, QKVS_SMEM);
    cudaFuncSetAttribute(k_hw_mma,   cudaFuncAttributeMaxDynamicSharedMemorySize, HW_SMEM);

    k_init_h1<<<NUM_TX, 128>>>(tx_x, W1, b1);

    const int edge_warp_blocks = (NE * 32 + 255) / 256;
    for (int t = 0; t < T_TYPES; t++) {
        const int* src_t = esrc + (size_t)t * NE;
        const int* dst_t = edst + (size_t)t * NE;
        k_reset   <<<(N_ENT * H + 255) / 256, 256>>>();
        k_qkvs_mma<<<dim3(148, 2), 512, QKVS_SMEM>>>(emb + (size_t)t * N_ENT * H,
                                                     eidx + (size_t)t * N_ENT,
                                                     Wq, bq, Wk, bk, Wv, bv, Ws, bs);
        k_score   <<<edge_warp_blocks, 256>>>(src_t, dst_t);
        k_exp     <<<(NE + 255) / 256, 256>>>(dst_t);
        k_msg     <<<edge_warp_blocks, 256>>>(src_t, dst_t);
        k_ln      <<<N_ENT, 128>>>(lns + t * H, lnb + t * H);
        k_hw_mma  <<<148, 512, HW_SMEM>>>(W1 + (size_t)(TXF + t * H) * H);
        k_scatter <<<edge_warp_blocks, 256>>>(src_t, dst_t);
    }

    k_mlp<<<NUM_TX, 64>>>(W2, b2, W3, b3, out);
}

// round 4
// speedup vs baseline: 1.7055x; 1.2572x over previous
#include <cuda_runtime.h>
#include <cuda_bf16.h>
#include <math.h>
#include <stdint.h>

#define T_TYPES 11
#define NUM_TX  131072
#define N_ENT   131072
#define NE      262144
#define H       128
#define TXF     394
#define LN_EPS  1e-5f
#define INV_SQRT_D 0.08838834764831845f   // 1/sqrt(128)

// bf16 tile strides (bytes): 128 bf16 = 256B + 16B pad -> conflict-free ldmatrix
#define SA 272
#define ATILE   34816     // 128 rows * 272B
#define ATILE2  69632     // 256 rows * 272B
#define BTILE   34816     // 128 n-rows * 272B

// ---------------- scratch (device globals; no cudaMalloc allowed) ----------
__device__ float g_q  [(size_t)N_ENT * H];
__device__ float g_k  [(size_t)N_ENT * H];
__device__ float g_v  [(size_t)N_ENT * H];
__device__ float g_hr [(size_t)N_ENT * H];   // root skip, then LN output h
__device__ float g_hw [(size_t)N_ENT * H];   // h @ W1_t
__device__ float g_h1 [(size_t)NUM_TX * H];  // layer-1 pre-activation accumulator

// CSR over dst, per type
__device__ int g_deg [T_TYPES][N_ENT];
__device__ int g_ptr [T_TYPES][N_ENT];
__device__ int g_cur [T_TYPES][N_ENT];
__device__ int g_col [T_TYPES][NE];
__device__ int g_bsum[T_TYPES][64];          // 131072 / 2048 chunks

// ================= helpers ===================================================
__device__ __forceinline__ uint32_t smem_u32(const void* p) {
    uint32_t a;
    asm("{ .reg .u64 t; cvta.to.shared.u64 t, %1; cvt.u32.u64 %0, t; }" : "=r"(a) : "l"(p));
    return a;
}
__device__ __forceinline__ void ldmx4(uint32_t* r, uint32_t addr) {
    asm volatile("ldmatrix.sync.aligned.m8n8.x4.shared.b16 {%0,%1,%2,%3}, [%4];"
        : "=r"(r[0]), "=r"(r[1]), "=r"(r[2]), "=r"(r[3]) : "r"(addr));
}
__device__ __forceinline__ void mma_bf16(float* c, const uint32_t* a, uint32_t b0, uint32_t b1) {
    asm volatile("mma.sync.aligned.m16n8k16.row.col.f32.bf16.bf16.f32 "
        "{%0,%1,%2,%3}, {%4,%5,%6,%7}, {%8,%9}, {%0,%1,%2,%3};"
        : "+f"(c[0]), "+f"(c[1]), "+f"(c[2]), "+f"(c[3])
        : "r"(a[0]), "r"(a[1]), "r"(a[2]), "r"(a[3]), "r"(b0), "r"(b1));
}
__device__ __forceinline__ uint32_t bfpack(float a, float b) {
    __nv_bfloat162 t = __floats2bfloat162_rn(a, b);
    return reinterpret_cast<uint32_t&>(t);
}
__device__ __forceinline__ void split4(float4 v, uint32_t* hi, uint32_t* lo) {
    __nv_bfloat16 hx = __float2bfloat16(v.x), hy = __float2bfloat16(v.y);
    __nv_bfloat16 hz = __float2bfloat16(v.z), hw = __float2bfloat16(v.w);
    __nv_bfloat162 h01; h01.x = hx; h01.y = hy;
    __nv_bfloat162 h23; h23.x = hz; h23.y = hw;
    hi[0] = reinterpret_cast<uint32_t&>(h01);
    hi[1] = reinterpret_cast<uint32_t&>(h23);
    lo[0] = bfpack(v.x - __bfloat162float(hx), v.y - __bfloat162float(hy));
    lo[1] = bfpack(v.z - __bfloat162float(hz), v.w - __bfloat162float(hw));
}

// ================= CSR build =================================================
__global__ void k_zero_deg() {
    const int i = blockIdx.x * blockDim.x + threadIdx.x;
    if (i < T_TYPES * N_ENT) ((int*)g_deg)[i] = 0;
}
__global__ void k_count(const int* __restrict__ edst) {
    const int i = blockIdx.x * blockDim.x + threadIdx.x;
    if (i >= T_TYPES * NE) return;
    const int t = i / NE;
    atomicAdd(&g_deg[t][edst[i]], 1);
}
// block = 256 threads scans 2048 entries
__global__ void k_scanA() {
    const int t = blockIdx.x >> 6, c = blockIdx.x & 63;
    const int base = c * 2048, tid = threadIdx.x;
    int v[8], s = 0;
    #pragma unroll
    for (int j = 0; j < 8; j++) { v[j] = g_deg[t][base + tid * 8 + j]; s += v[j]; }
    __shared__ int sm[256];
    sm[tid] = s; __syncthreads();
    for (int off = 1; off < 256; off <<= 1) {
        int x = (tid >= off) ? sm[tid - off] : 0;
        __syncthreads();
        sm[tid] += x;
        __syncthreads();
    }
    int run = (tid == 0) ? 0 : sm[tid - 1];
    if (tid == 255) g_bsum[t][c] = sm[255];
    #pragma unroll
    for (int j = 0; j < 8; j++) { g_ptr[t][base + tid * 8 + j] = run; run += v[j]; }
}
__global__ void k_scanB() {   // 11 blocks x 64 threads: exclusive scan of chunk sums
    const int t = blockIdx.x, tid = threadIdx.x;
    __shared__ int sm[64];
    sm[tid] = g_bsum[t][tid]; __syncthreads();
    for (int off = 1; off < 64; off <<= 1) {
        int x = (tid >= off) ? sm[tid - off] : 0;
        __syncthreads();
        sm[tid] += x;
        __syncthreads();
    }
    g_bsum[t][tid] = (tid == 0) ? 0 : sm[tid - 1];
    __syncthreads();
}
__global__ void k_scanC() {
    const int t = blockIdx.x >> 6, c = blockIdx.x & 63;
    const int base = c * 2048, tid = threadIdx.x;
    const int add = g_bsum[t][c];
    #pragma unroll
    for (int j = 0; j < 8; j++) {
        const int i = base + tid * 8 + j;
        const int p = g_ptr[t][i] + add;
        g_ptr[t][i] = p;
        g_cur[t][i] = p;
    }
}
__global__ void k_fill(const int* __restrict__ esrc, const int* __restrict__ edst) {
    const int i = blockIdx.x * blockDim.x + threadIdx.x;
    if (i >= T_TYPES * NE) return;
    const int t = i / NE;
    const int slot = atomicAdd(&g_cur[t][edst[i]], 1);
    g_col[t][slot] = esrc[i];
}

// ================= h1 init: b1 + tx_x @ W1[0:394, :] ========================
__global__ void k_init_h1(const float* __restrict__ tx,
                          const float* __restrict__ W1,
                          const float* __restrict__ b1) {
    __shared__ float xs[TXF];
    const int row = blockIdx.x;
    const int tid = threadIdx.x;           // 128 threads
    const float* trow = tx + (size_t)row * TXF;
    for (int i = tid; i < TXF; i += 128) xs[i] = trow[i];
    __syncthreads();
    float acc = b1[tid];
    #pragma unroll 2
    for (int k = 0; k < TXF; k++) acc = fmaf(xs[k], W1[k * H + tid], acc);
    g_h1[(size_t)row * H + tid] = acc;
}

// ================= HMMA qkvs: gather + 2 GEMMs per y-half ===================
__global__ void __launch_bounds__(512, 1) k_qkvs_mma(
    const float* __restrict__ emb, const int* __restrict__ idx,
    const float* __restrict__ Wq, const float* __restrict__ bq,
    const float* __restrict__ Wk, const float* __restrict__ bk,
    const float* __restrict__ Wv, const float* __restrict__ bv,
    const float* __restrict__ Ws, const float* __restrict__ bs)
{
    extern __shared__ char dsraw[];
    const uint32_t raw  = smem_u32(dsraw);
    const uint32_t base = (raw + 1023u) & ~1023u;
    char* dsm = dsraw + (base - raw);

    const int tid = threadIdx.x, warp = tid >> 5, lane = tid & 31;

    const float *W0, *W1m, *bb0, *bb1;
    float *o0, *o1;
    if (blockIdx.y == 0) { W0 = Wq; bb0 = bq; W1m = Wk; bb1 = bk; o0 = g_q; o1 = g_k;  }
    else                 { W0 = Wv; bb0 = bv; W1m = Ws; bb1 = bs; o0 = g_v; o1 = g_hr; }

    char* Ahp = dsm;
    char* Alp = dsm + ATILE;
    char* Bp  = dsm + 2 * ATILE;
    float* bias = (float*)(dsm + 2 * ATILE + 4 * BTILE);

    for (int o = 0; o < 2; o++) {
        const float* W = o ? W1m : W0;
        char* bh = Bp + o * 2 * BTILE;
        char* bl = bh + BTILE;
        for (int i = tid; i < H * H; i += 512) {
            const int k = i >> 7, n = i & 127;
            const float w = W[i];
            const __nv_bfloat16 h = __float2bfloat16(w);
            *(__nv_bfloat16*)(bh + n * SA + k * 2) = h;
            *(__nv_bfloat16*)(bl + n * SA + k * 2) =
                __float2bfloat16(w - __bfloat162float(h));
        }
    }
    for (int i = tid; i < 256; i += 512) bias[i] = (i < 128) ? bb0[i] : bb1[i - 128];
    __syncthreads();

    const uint32_t AhA = smem_u32(Ahp), AlA = smem_u32(Alp);
    const int out = warp >> 3;
    const int rbw = ((warp >> 1) & 3) * 32;
    const int ch  = warp & 1;
    const uint32_t BhA = smem_u32(Bp + out * 2 * BTILE);
    const uint32_t BlA = BhA + BTILE;
    float* const outp = out ? o1 : o0;

    for (int tile = blockIdx.x; tile < N_ENT / 128; tile += gridDim.x) {
        const int rb = tile * 128;
        {
            const int r = tid >> 2, cq = tid & 3;
            const int e = __ldg(idx + rb + r);
            const float4* src = (const float4*)(emb + (size_t)e * H) + cq * 8;
            char* ah = Ahp + r * SA + cq * 64;
            char* al = Alp + r * SA + cq * 64;
            #pragma unroll
            for (int j = 0; j < 8; j++) {
                uint32_t hi[2], lo[2];
                split4(__ldg(src + j), hi, lo);
                *(uint32_t*)(ah + j * 8)     = hi[0];
                *(uint32_t*)(ah + j * 8 + 4) = hi[1];
                *(uint32_t*)(al + j * 8)     = lo[0];
                *(uint32_t*)(al + j * 8 + 4) = lo[1];
            }
        }
        __syncthreads();

        float acc[2][8][4];
        #pragma unroll
        for (int mt = 0; mt < 2; mt++)
            #pragma unroll
            for (int nt = 0; nt < 8; nt++)
                #pragma unroll
                for (int q = 0; q < 4; q++) acc[mt][nt][q] = 0.0f;

        const uint32_t arow = rbw + (lane & 15);
        const uint32_t aqof = (lane >> 4) * 16;
        const uint32_t brow = ch * 64 + ((lane >> 4) * 8) + (lane & 7);
        const uint32_t bqof = ((lane >> 3) & 1) * 16;

        #pragma unroll
        for (int ks = 0; ks < 8; ks++) {
            const uint32_t kb = ks * 32;
            uint32_t ah[2][4], al[2][4], bf[4][4];
            #pragma unroll
            for (int mt = 0; mt < 2; mt++) {
                const uint32_t ao = (arow + mt * 16) * SA + kb + aqof;
                ldmx4(ah[mt], AhA + ao);
                ldmx4(al[mt], AlA + ao);
            }
            #pragma unroll
            for (int np = 0; np < 4; np++)
                ldmx4(bf[np], BhA + (brow + np * 16) * SA + kb + bqof);
            #pragma unroll
            for (int np = 0; np < 4; np++)
                #pragma unroll
                for (int sb = 0; sb < 2; sb++) {
                    const int nt = np * 2 + sb;
                    #pragma unroll
                    for (int mt = 0; mt < 2; mt++) {
                        mma_bf16(acc[mt][nt], ah[mt], bf[np][sb*2], bf[np][sb*2+1]);
                        mma_bf16(acc[mt][nt], al[mt], bf[np][sb*2], bf[np][sb*2+1]);
                    }
                }
            #pragma unroll
            for (int np = 0; np < 4; np++)
                ldmx4(bf[np], BlA + (brow + np * 16) * SA + kb + bqof);
            #pragma unroll
            for (int np = 0; np < 4; np++)
                #pragma unroll
                for (int sb = 0; sb < 2; sb++) {
                    const int nt = np * 2 + sb;
                    #pragma unroll
                    for (int mt = 0; mt < 2; mt++)
                        mma_bf16(acc[mt][nt], ah[mt], bf[np][sb*2], bf[np][sb*2+1]);
                }
        }

        #pragma unroll
        for (int mt = 0; mt < 2; mt++) {
            const int row0 = rb + rbw + mt * 16 + (lane >> 2);
            #pragma unroll
            for (int nt = 0; nt < 8; nt++) {
                const int col = ch * 64 + nt * 8 + (lane & 3) * 2;
                const float bv0 = bias[out * 128 + col], bv1 = bias[out * 128 + col + 1];
                float2 v0 = { acc[mt][nt][0] + bv0, acc[mt][nt][1] + bv1 };
                float2 v1 = { acc[mt][nt][2] + bv0, acc[mt][nt][3] + bv1 };
                *(float2*)(outp + (size_t)row0 * H + col)       = v0;
                *(float2*)(outp + (size_t)(row0 + 8) * H + col) = v1;
            }
        }
        __syncthreads();
    }
}

// ================= fused attention + LN (warp per dst) ======================
// msg = sum_e exp(sc_e) v[src_e] / sum_e exp(sc_e);  h = LN(msg + hr)*g + b
__global__ void __launch_bounds__(256) k_attn(int t,
        const float* __restrict__ lns, const float* __restrict__ lnb) {
    const int warp = threadIdx.x >> 5, lane = threadIdx.x & 31;
    const int d = blockIdx.x * 8 + warp;
    const float4 q4 = ((const float4*)(g_q + (size_t)d * H))[lane];
    const int start = g_ptr[t][d], deg = g_deg[t][d];

    float den = 0.0f;
    float4 acc = {0.0f, 0.0f, 0.0f, 0.0f};
    for (int e = 0; e < deg; e++) {
        const int s = g_col[t][start + e];
        const float4 k4 = ((const float4*)(g_k + (size_t)s * H))[lane];
        const float4 v4 = ((const float4*)(g_v + (size_t)s * H))[lane];
        float dot = q4.x * k4.x + q4.y * k4.y + q4.z * k4.z + q4.w * k4.w;
        #pragma unroll
        for (int o = 16; o; o >>= 1) dot += __shfl_xor_sync(0xffffffffu, dot, o);
        const float w = expf(dot * INV_SQRT_D);
        den += w;
        acc.x += w * v4.x; acc.y += w * v4.y; acc.z += w * v4.z; acc.w += w * v4.w;
    }
    float4 h4 = ((const float4*)(g_hr + (size_t)d * H))[lane];
    const float inv = (deg > 0) ? 1.0f / den : 0.0f;
    h4.x += acc.x * inv; h4.y += acc.y * inv;
    h4.z += acc.z * inv; h4.w += acc.w * inv;

    float s1 = h4.x + h4.y + h4.z + h4.w;
    float s2 = h4.x * h4.x + h4.y * h4.y + h4.z * h4.z + h4.w * h4.w;
    #pragma unroll
    for (int o = 16; o; o >>= 1) {
        s1 += __shfl_xor_sync(0xffffffffu, s1, o);
        s2 += __shfl_xor_sync(0xffffffffu, s2, o);
    }
    const float mu  = s1 * (1.0f / H);
    const float var = s2 * (1.0f / H) - mu * mu;
    const float rstd = rsqrtf(var + LN_EPS);
    const float4 g4 = ((const float4*)lns)[lane];
    const float4 b4 = ((const float4*)lnb)[lane];
    float4 o4;
    o4.x = (h4.x - mu) * rstd * g4.x + b4.x;
    o4.y = (h4.y - mu) * rstd * g4.y + b4.y;
    o4.z = (h4.z - mu) * rstd * g4.z + b4.z;
    o4.w = (h4.w - mu) * rstd * g4.w + b4.w;
    ((float4*)(g_hr + (size_t)d * H))[lane] = o4;
}

// ================= HMMA hw = h @ W1_t (256-row tiles) ========================
__global__ void __launch_bounds__(512, 1) k_hw_mma(const float* __restrict__ W1t)
{
    extern __shared__ char dsraw[];
    const uint32_t raw  = smem_u32(dsraw);
    const uint32_t base = (raw + 1023u) & ~1023u;
    char* dsm = dsraw + (base - raw);

    const int tid = threadIdx.x, warp = tid >> 5, lane = tid & 31;

    char* Ahp = dsm;
    char* Alp = dsm + ATILE2;
    char* Bhp = dsm + 2 * ATILE2;
    char* Blp = Bhp + BTILE;

    for (int i = tid; i < H * H; i += 512) {
        const int k = i >> 7, n = i & 127;
        const float w = W1t[i];
        const __nv_bfloat16 h = __float2bfloat16(w);
        *(__nv_bfloat16*)(Bhp + n * SA + k * 2) = h;
        *(__nv_bfloat16*)(Blp + n * SA + k * 2) = __float2bfloat16(w - __bfloat162float(h));
    }
    __syncthreads();

    const uint32_t AhA = smem_u32(Ahp), AlA = smem_u32(Alp);
    const uint32_t BhA = smem_u32(Bhp), BlA = smem_u32(Blp);
    const int rbw = (warp & 7) * 32;
    const int ch  = warp >> 3;

    for (int tile = blockIdx.x; tile < N_ENT / 256; tile += gridDim.x) {
        const int rb = tile * 256;
        {
            const int r = tid >> 1, hf = tid & 1;
            const float4* src = (const float4*)(g_hr + (size_t)(rb + r) * H) + hf * 16;
            char* ah = Ahp + r * SA + hf * 128;
            char* al = Alp + r * SA + hf * 128;
            #pragma unroll
            for (int j = 0; j < 16; j++) {
                uint32_t hi[2], lo[2];
                split4(__ldg(src + j), hi, lo);
                *(uint32_t*)(ah + j * 8)     = hi[0];
                *(uint32_t*)(ah + j * 8 + 4) = hi[1];
                *(uint32_t*)(al + j * 8)     = lo[0];
                *(uint32_t*)(al + j * 8 + 4) = lo[1];
            }
        }
        __syncthreads();

        float acc[2][8][4];
        #pragma unroll
        for (int mt = 0; mt < 2; mt++)
            #pragma unroll
            for (int nt = 0; nt < 8; nt++)
                #pragma unroll
                for (int q = 0; q < 4; q++) acc[mt][nt][q] = 0.0f;

        const uint32_t arow = rbw + (lane & 15);
        const uint32_t aqof = (lane >> 4) * 16;
        const uint32_t brow = ch * 64 + ((lane >> 4) * 8) + (lane & 7);
        const uint32_t bqof = ((lane >> 3) & 1) * 16;

        #pragma unroll
        for (int ks = 0; ks < 8; ks++) {
            const uint32_t kb = ks * 32;
            uint32_t ah[2][4], al[2][4], bf[4][4];
            #pragma unroll
            for (int mt = 0; mt < 2; mt++) {
                const uint32_t ao = (arow + mt * 16) * SA + kb + aqof;
                ldmx4(ah[mt], AhA + ao);
                ldmx4(al[mt], AlA + ao);
            }
            #pragma unroll
            for (int np = 0; np < 4; np++)
                ldmx4(bf[np], BhA + (brow + np * 16) * SA + kb + bqof);
            #pragma unroll
            for (int np = 0; np < 4; np++)
                #pragma unroll
                for (int sb = 0; sb < 2; sb++) {
                    const int nt = np * 2 + sb;
                    #pragma unroll
                    for (int mt = 0; mt < 2; mt++) {
                        mma_bf16(acc[mt][nt], ah[mt], bf[np][sb*2], bf[np][sb*2+1]);
                        mma_bf16(acc[mt][nt], al[mt], bf[np][sb*2], bf[np][sb*2+1]);
                    }
                }
            #pragma unroll
            for (int np = 0; np < 4; np++)
                ldmx4(bf[np], BlA + (brow + np * 16) * SA + kb + bqof);
            #pragma unroll
            for (int np = 0; np < 4; np++)
                #pragma unroll
                for (int sb = 0; sb < 2; sb++) {
                    const int nt = np * 2 + sb;
                    #pragma unroll
                    for (int mt = 0; mt < 2; mt++)
                        mma_bf16(acc[mt][nt], ah[mt], bf[np][sb*2], bf[np][sb*2+1]);
                }
        }

        #pragma unroll
        for (int mt = 0; mt < 2; mt++) {
            const int row0 = rb + rbw + mt * 16 + (lane >> 2);
            #pragma unroll
            for (int nt = 0; nt < 8; nt++) {
                const int col = ch * 64 + nt * 8 + (lane & 3) * 2;
                float2 v0 = { acc[mt][nt][0], acc[mt][nt][1] };
                float2 v1 = { acc[mt][nt][2], acc[mt][nt][3] };
                *(float2*)(g_hw + (size_t)row0 * H + col)       = v0;
                *(float2*)(g_hw + (size_t)(row0 + 8) * H + col) = v1;
            }
        }
        __syncthreads();
    }
}

// ================= h1[d] += sum_e hw[col[e]]  (warp per dst) =================
__global__ void __launch_bounds__(256) k_h1add(int t) {
    const int warp = threadIdx.x >> 5, lane = threadIdx.x & 31;
    const int d = blockIdx.x * 8 + warp;
    const int start = g_ptr[t][d], deg = g_deg[t][d];
    if (deg == 0) return;
    float4 acc = {0.0f, 0.0f, 0.0f, 0.0f};
    for (int e = 0; e < deg; e++) {
        const int s = g_col[t][start + e];
        const float4 w4 = ((const float4*)(g_hw + (size_t)s * H))[lane];
        acc.x += w4.x; acc.y += w4.y; acc.z += w4.z; acc.w += w4.w;
    }
    float4* p = (float4*)(g_h1 + (size_t)d * H) + lane;
    float4 cur = *p;
    cur.x += acc.x; cur.y += acc.y; cur.z += acc.z; cur.w += acc.w;
    *p = cur;
}

// ================= tail MLP: relu -> W2(64) relu -> W3(1) ====================
__global__ void k_mlp(const float* __restrict__ W2, const float* __restrict__ b2,
                      const float* __restrict__ W3, const float* __restrict__ b3,
                      float* __restrict__ out) {
    __shared__ float h1s[H];
    __shared__ float red[2];
    const int row = blockIdx.x, tid = threadIdx.x;   // 64 threads
    h1s[tid]      = fmaxf(g_h1[(size_t)row * H + tid],      0.0f);
    h1s[tid + 64] = fmaxf(g_h1[(size_t)row * H + tid + 64], 0.0f);
    __syncthreads();
    float acc = b2[tid];
    #pragma unroll 4
    for (int k = 0; k < H; k++) acc = fmaf(h1s[k], W2[k * 64 + tid], acc);
    float v = fmaxf(acc, 0.0f) * W3[tid];
    #pragma unroll
    for (int o = 16; o; o >>= 1) v += __shfl_xor_sync(0xffffffffu, v, o);
    if ((tid & 31) == 0) red[tid >> 5] = v;
    __syncthreads();
    if (tid == 0) out[row] = red[0] + red[1] + b3[0];
}

// ================= host launcher =============================================
extern "C" void kernel_launch(void* const* d_in, const int* in_sizes, int n_in,
                              void* d_out, int out_size) {
    const float* tx_x = (const float*)d_in[0];
    const float* emb  = (const float*)d_in[1];
    const int*   eidx = (const int*)  d_in[2];
    const int*   esrc = (const int*)  d_in[3];
    const int*   edst = (const int*)  d_in[4];
    const float* Wq = (const float*)d_in[5],  *bq = (const float*)d_in[6];
    const float* Wk = (const float*)d_in[7],  *bk = (const float*)d_in[8];
    const float* Wv = (const float*)d_in[9],  *bv = (const float*)d_in[10];
    const float* Ws = (const float*)d_in[11], *bs = (const float*)d_in[12];
    const float* lns = (const float*)d_in[13], *lnb = (const float*)d_in[14];
    const float* W1 = (const float*)d_in[15], *b1 = (const float*)d_in[16];
    const float* W2 = (const float*)d_in[17], *b2 = (const float*)d_in[18];
    const float* W3 = (const float*)d_in[19], *b3 = (const float*)d_in[20];
    float* out = (float*)d_out;

    const int QKVS_SMEM = 2 * ATILE + 4 * BTILE + 1024 + 1024;
    const int HW_SMEM   = 2 * ATILE2 + 2 * BTILE + 1024;
    cudaFuncSetAttribute(k_qkvs_mma, cudaFuncAttributeMaxDynamicSharedMemorySize, QKVS_SMEM);
    cudaFuncSetAttribute(k_hw_mma,   cudaFuncAttributeMaxDynamicSharedMemorySize, HW_SMEM);

    // ---- CSR build (all 11 types) ----
    k_zero_deg<<<(T_TYPES * N_ENT + 255) / 256, 256>>>();
    k_count   <<<(T_TYPES * NE + 255) / 256, 256>>>(edst);
    k_scanA   <<<T_TYPES * 64, 256>>>();
    k_scanB   <<<T_TYPES, 64>>>();
    k_scanC   <<<T_TYPES * 64, 256>>>();
    k_fill    <<<(T_TYPES * NE + 255) / 256, 256>>>(esrc, edst);

    k_init_h1<<<NUM_TX, 128>>>(tx_x, W1, b1);

    for (int t = 0; t < T_TYPES; t++) {
        k_qkvs_mma<<<dim3(148, 2), 512, QKVS_SMEM>>>(emb + (size_t)t * N_ENT * H,
                                                     eidx + (size_t)t * N_ENT,
                                                     Wq, bq, Wk, bk, Wv, bv, Ws, bs);
        k_attn    <<<N_ENT / 8, 256>>>(t, lns + t * H, lnb + t * H);
        k_hw_mma  <<<148, 512, HW_SMEM>>>(W1 + (size_t)(TXF + t * H) * H);
        k_h1add   <<<NUM_TX / 8, 256>>>(t);
    }

    k_mlp<<<NUM_TX, 64>>>(W2, b2, W3, b3, out);
}

// round 5
// speedup vs baseline: 2.1123x; 1.2385x over previous
#include <cuda_runtime.h>
#include <cuda_bf16.h>
#include <math.h>
#include <stdint.h>

#define T_TYPES 11
#define NUM_TX  131072
#define N_ENT   131072
#define NE      262144
#define H       128
#define TXF     394
#define LN_EPS  1e-5f
#define INV_SQRT_D 0.08838834764831845f   // 1/sqrt(128)

// bf16 tile strides (bytes): 128 bf16 = 256B + 16B pad -> conflict-free ldmatrix
#define SA 272
#define ATILE   34816     // 128 rows * 272B
#define ATILE2  69632     // 256 rows * 272B
#define BTILE   34816     // 128 n-rows * 272B

// ---------------- scratch (device globals; no cudaMalloc allowed) ----------
__device__ float g_z   [(size_t)N_ENT * H];   // x @ (Wk Wq^T)
__device__ float g_x   [(size_t)N_ENT * H];   // gathered embeddings
__device__ float g_xagg[(size_t)N_ENT * H];   // sum_e alpha x[src]
__device__ float g_hr  [(size_t)N_ENT * H];   // LN output h
__device__ float g_hw  [(size_t)N_ENT * H];   // h @ W1_t
__device__ float g_h1  [(size_t)NUM_TX * H];  // layer-1 pre-activation accumulator
__device__ float g_c   [N_ENT];               // x_s . (Wk bq)
__device__ float g_weff[H * H];               // Wz[k][n]
__device__ float g_wkbq[H];

// CSR over dst, per type
__device__ int g_deg [T_TYPES][N_ENT];
__device__ int g_ptr [T_TYPES][N_ENT];
__device__ int g_cur [T_TYPES][N_ENT];
__device__ int g_col [T_TYPES][NE];
__device__ int g_bsum[T_TYPES][64];

// ================= helpers ===================================================
__device__ __forceinline__ uint32_t smem_u32(const void* p) {
    uint32_t a;
    asm("{ .reg .u64 t; cvta.to.shared.u64 t, %1; cvt.u32.u64 %0, t; }" : "=r"(a) : "l"(p));
    return a;
}
__device__ __forceinline__ void ldmx4(uint32_t* r, uint32_t addr) {
    asm volatile("ldmatrix.sync.aligned.m8n8.x4.shared.b16 {%0,%1,%2,%3}, [%4];"
        : "=r"(r[0]), "=r"(r[1]), "=r"(r[2]), "=r"(r[3]) : "r"(addr));
}
__device__ __forceinline__ void mma_bf16(float* c, const uint32_t* a, uint32_t b0, uint32_t b1) {
    asm volatile("mma.sync.aligned.m16n8k16.row.col.f32.bf16.bf16.f32 "
        "{%0,%1,%2,%3}, {%4,%5,%6,%7}, {%8,%9}, {%0,%1,%2,%3};"
        : "+f"(c[0]), "+f"(c[1]), "+f"(c[2]), "+f"(c[3])
        : "r"(a[0]), "r"(a[1]), "r"(a[2]), "r"(a[3]), "r"(b0), "r"(b1));
}
__device__ __forceinline__ uint32_t bfpack(float a, float b) {
    __nv_bfloat162 t = __floats2bfloat162_rn(a, b);
    return reinterpret_cast<uint32_t&>(t);
}
__device__ __forceinline__ void split4(float4 v, uint32_t* hi, uint32_t* lo) {
    __nv_bfloat16 hx = __float2bfloat16(v.x), hy = __float2bfloat16(v.y);
    __nv_bfloat16 hz = __float2bfloat16(v.z), hw = __float2bfloat16(v.w);
    __nv_bfloat162 h01; h01.x = hx; h01.y = hy;
    __nv_bfloat162 h23; h23.x = hz; h23.y = hw;
    hi[0] = reinterpret_cast<uint32_t&>(h01);
    hi[1] = reinterpret_cast<uint32_t&>(h23);
    lo[0] = bfpack(v.x - __bfloat162float(hx), v.y - __bfloat162float(hy));
    lo[1] = bfpack(v.z - __bfloat162float(hz), v.w - __bfloat162float(hw));
}

// convert fp32 weight (x@W layout) into split-bf16 B tiles: B[n][k] = W[k][n]
__device__ __forceinline__ void conv_B(const float* __restrict__ W, char* bh, char* bl,
                                       int tid, int nthr) {
    for (int i = tid; i < H * H; i += nthr) {
        const int k = i >> 7, n = i & 127;
        const float w = W[i];
        const __nv_bfloat16 h = __float2bfloat16(w);
        *(__nv_bfloat16*)(bh + n * SA + k * 2) = h;
        *(__nv_bfloat16*)(bl + n * SA + k * 2) = __float2bfloat16(w - __bfloat162float(h));
    }
}

// ================= prep: Wz = Wk Wq^T, wkbq = Wk bq ==========================
__global__ void k_prep(const float* __restrict__ Wq, const float* __restrict__ Wk,
                       const float* __restrict__ bq) {
    __shared__ float wkrow[H];
    const int b = blockIdx.x, a = threadIdx.x;
    wkrow[a] = Wk[b * H + a];
    __syncthreads();
    float s = 0.0f;
    #pragma unroll 4
    for (int j = 0; j < H; j++) s = fmaf(wkrow[j], Wq[a * H + j], s);
    g_weff[b * H + a] = s;           // Wz[k=b][n=a]
    if (b == 0) {
        float t = 0.0f;
        for (int j = 0; j < H; j++) t = fmaf(Wk[a * H + j], bq[j], t);
        g_wkbq[a] = t;
    }
}

// ================= CSR build =================================================
__global__ void k_zero_deg() {
    const int i = blockIdx.x * blockDim.x + threadIdx.x;
    if (i < T_TYPES * N_ENT) ((int*)g_deg)[i] = 0;
}
__global__ void k_count(const int* __restrict__ edst) {
    const int i = blockIdx.x * blockDim.x + threadIdx.x;
    if (i >= T_TYPES * NE) return;
    const int t = i / NE;
    atomicAdd(&g_deg[t][edst[i]], 1);
}
__global__ void k_scanA() {
    const int t = blockIdx.x >> 6, c = blockIdx.x & 63;
    const int base = c * 2048, tid = threadIdx.x;
    int v[8], s = 0;
    #pragma unroll
    for (int j = 0; j < 8; j++) { v[j] = g_deg[t][base + tid * 8 + j]; s += v[j]; }
    __shared__ int sm[256];
    sm[tid] = s; __syncthreads();
    for (int off = 1; off < 256; off <<= 1) {
        int x = (tid >= off) ? sm[tid - off] : 0;
        __syncthreads();
        sm[tid] += x;
        __syncthreads();
    }
    int run = (tid == 0) ? 0 : sm[tid - 1];
    if (tid == 255) g_bsum[t][c] = sm[255];
    #pragma unroll
    for (int j = 0; j < 8; j++) { g_ptr[t][base + tid * 8 + j] = run; run += v[j]; }
}
__global__ void k_scanB() {
    const int t = blockIdx.x, tid = threadIdx.x;
    __shared__ int sm[64];
    sm[tid] = g_bsum[t][tid]; __syncthreads();
    for (int off = 1; off < 64; off <<= 1) {
        int x = (tid >= off) ? sm[tid - off] : 0;
        __syncthreads();
        sm[tid] += x;
        __syncthreads();
    }
    g_bsum[t][tid] = (tid == 0) ? 0 : sm[tid - 1];
}
__global__ void k_scanC() {
    const int t = blockIdx.x >> 6, c = blockIdx.x & 63;
    const int base = c * 2048, tid = threadIdx.x;
    const int add = g_bsum[t][c];
    #pragma unroll
    for (int j = 0; j < 8; j++) {
        const int i = base + tid * 8 + j;
        const int p = g_ptr[t][i] + add;
        g_ptr[t][i] = p;
        g_cur[t][i] = p;
    }
}
__global__ void k_fill(const int* __restrict__ esrc, const int* __restrict__ edst) {
    const int i = blockIdx.x * blockDim.x + threadIdx.x;
    if (i >= T_TYPES * NE) return;
    const int t = i / NE;
    const int slot = atomicAdd(&g_cur[t][edst[i]], 1);
    g_col[t][slot] = esrc[i];
}

// ================= MMA core (256-row tile, acc[2][8][4], 16 warps) ==========
#define MMA_TILE256(AhA, AlA, BhA, BlA, acc, rbw, ch, lane)                          \
    {                                                                                 \
        const uint32_t arow = (rbw) + ((lane) & 15);                                  \
        const uint32_t aqof = ((lane) >> 4) * 16;                                     \
        const uint32_t brow = (ch) * 64 + (((lane) >> 4) * 8) + ((lane) & 7);         \
        const uint32_t bqof = (((lane) >> 3) & 1) * 16;                               \
        _Pragma("unroll")                                                             \
        for (int ks = 0; ks < 8; ks++) {                                              \
            const uint32_t kb = ks * 32;                                              \
            uint32_t ah[2][4], al[2][4], bf[4][4];                                    \
            _Pragma("unroll")                                                         \
            for (int mt = 0; mt < 2; mt++) {                                          \
                const uint32_t ao = (arow + mt * 16) * SA + kb + aqof;                \
                ldmx4(ah[mt], (AhA) + ao);                                            \
                ldmx4(al[mt], (AlA) + ao);                                            \
            }                                                                         \
            _Pragma("unroll")                                                         \
            for (int np = 0; np < 4; np++)                                            \
                ldmx4(bf[np], (BhA) + (brow + np * 16) * SA + kb + bqof);             \
            _Pragma("unroll")                                                         \
            for (int np = 0; np < 4; np++)                                            \
                _Pragma("unroll")                                                     \
                for (int sb = 0; sb < 2; sb++) {                                      \
                    const int nt = np * 2 + sb;                                       \
                    _Pragma("unroll")                                                 \
                    for (int mt = 0; mt < 2; mt++) {                                  \
                        mma_bf16(acc[mt][nt], ah[mt], bf[np][sb*2], bf[np][sb*2+1]);  \
                        mma_bf16(acc[mt][nt], al[mt], bf[np][sb*2], bf[np][sb*2+1]);  \
                    }                                                                 \
                }                                                                     \
            _Pragma("unroll")                                                         \
            for (int np = 0; np < 4; np++)                                            \
                ldmx4(bf[np], (BlA) + (brow + np * 16) * SA + kb + bqof);             \
            _Pragma("unroll")                                                         \
            for (int np = 0; np < 4; np++)                                            \
                _Pragma("unroll")                                                     \
                for (int sb = 0; sb < 2; sb++) {                                      \
                    const int nt = np * 2 + sb;                                       \
                    _Pragma("unroll")                                                 \
                    for (int mt = 0; mt < 2; mt++)                                    \
                        mma_bf16(acc[mt][nt], ah[mt], bf[np][sb*2], bf[np][sb*2+1]);  \
                }                                                                     \
        }                                                                             \
    }

// ================= init_h1 via MMA: b1 + tx_x @ W1[0:394] ====================
// K chunks: 128,128,128,16(10 real). 256-row tiles.
__global__ void __launch_bounds__(512, 1) k_init_mma(const float* __restrict__ tx,
                                                     const float* __restrict__ W1,
                                                     const float* __restrict__ b1) {
    extern __shared__ char dsraw[];
    __shared__ float s_b1[H];
    const uint32_t raw  = smem_u32(dsraw);
    const uint32_t base = (raw + 1023u) & ~1023u;
    char* dsm = dsraw + (base - raw);
    const int tid = threadIdx.x, warp = tid >> 5, lane = tid & 31;

    char* Ahp = dsm;
    char* Alp = dsm + ATILE2;
    char* Bhp = dsm + 2 * ATILE2;
    char* Blp = Bhp + BTILE;
    const uint32_t AhA = smem_u32(Ahp), AlA = smem_u32(Alp);
    const uint32_t BhA = smem_u32(Bhp), BlA = smem_u32(Blp);

    if (tid < H) s_b1[tid] = b1[tid];

    const int rbw = (warp & 7) * 32;
    const int ch  = warp >> 3;

    for (int tile = blockIdx.x; tile < NUM_TX / 256; tile += gridDim.x) {
        const int rb = tile * 256;
        float acc[2][8][4];
        #pragma unroll
        for (int mt = 0; mt < 2; mt++)
            #pragma unroll
            for (int nt = 0; nt < 8; nt++)
                #pragma unroll
                for (int q = 0; q < 4; q++) acc[mt][nt][q] = 0.0f;

        for (int chunk = 0; chunk < 4; chunk++) {
            __syncthreads();   // protect smem from previous mma reads
            const int kcols = (chunk < 3) ? 128 : 16;
            // B chunk: B[n][k] = W1[chunk*128+k][n], zero beyond TXF
            for (int i = tid; i < kcols * H; i += 512) {
                const int k = i >> 7, n = i & 127;
                const int kk = chunk * 128 + k;
                const float w = (kk < TXF) ? W1[(size_t)kk * H + n] : 0.0f;
                const __nv_bfloat16 h = __float2bfloat16(w);
                *(__nv_bfloat16*)(Bhp + n * SA + k * 2) = h;
                *(__nv_bfloat16*)(Blp + n * SA + k * 2) =
                    __float2bfloat16(w - __bfloat162float(h));
            }
            // A chunk: rows rb..rb+255, cols chunk*128 + [0,kcols)
            const int r = tid >> 1, hf = tid & 1;
            const float* rowp = tx + (size_t)(rb + r) * TXF;
            if (chunk < 3) {
                const float2* src = (const float2*)(rowp + chunk * 128 + hf * 64);
                char* ah = Ahp + r * SA + hf * 128;
                char* al = Alp + r * SA + hf * 128;
                #pragma unroll
                for (int j = 0; j < 16; j++) {
                    const float2 a = __ldg(src + j * 2);
                    const float2 b = __ldg(src + j * 2 + 1);
                    float4 v = { a.x, a.y, b.x, b.y };
                    uint32_t hi[2], lo[2];
                    split4(v, hi, lo);
                    *(uint32_t*)(ah + j * 8)     = hi[0];
                    *(uint32_t*)(ah + j * 8 + 4) = hi[1];
                    *(uint32_t*)(al + j * 8)     = lo[0];
                    *(uint32_t*)(al + j * 8 + 4) = lo[1];
                }
            } else {
                float vals[8];
                #pragma unroll
                for (int j = 0; j < 8; j++) {
                    const int c = 384 + hf * 8 + j;
                    vals[j] = (c < TXF) ? __ldg(rowp + c) : 0.0f;
                }
                char* ah = Ahp + r * SA + hf * 16;
                char* al = Alp + r * SA + hf * 16;
                #pragma unroll
                for (int p = 0; p < 4; p++) {
                    float4 v = { vals[p*2], vals[p*2+1], 0.0f, 0.0f };
                    uint32_t hi[2], lo[2];
                    split4(v, hi, lo);
                    *(uint32_t*)(ah + p * 4) = hi[0];
                    *(uint32_t*)(al + p * 4) = lo[0];
                }
            }
            __syncthreads();

            const uint32_t arow = rbw + (lane & 15);
            const uint32_t aqof = (lane >> 4) * 16;
            const uint32_t brow = ch * 64 + ((lane >> 4) * 8) + (lane & 7);
            const uint32_t bqof = ((lane >> 3) & 1) * 16;
            const int nks = (chunk < 3) ? 8 : 1;
            for (int ks = 0; ks < nks; ks++) {
                const uint32_t kb = ks * 32;
                uint32_t ah[2][4], al[2][4], bf[4][4];
                #pragma unroll
                for (int mt = 0; mt < 2; mt++) {
                    const uint32_t ao = (arow + mt * 16) * SA + kb + aqof;
                    ldmx4(ah[mt], AhA + ao);
                    ldmx4(al[mt], AlA + ao);
                }
                #pragma unroll
                for (int np = 0; np < 4; np++)
                    ldmx4(bf[np], BhA + (brow + np * 16) * SA + kb + bqof);
                #pragma unroll
                for (int np = 0; np < 4; np++)
                    #pragma unroll
                    for (int sb = 0; sb < 2; sb++) {
                        const int nt = np * 2 + sb;
                        #pragma unroll
                        for (int mt = 0; mt < 2; mt++) {
                            mma_bf16(acc[mt][nt], ah[mt], bf[np][sb*2], bf[np][sb*2+1]);
                            mma_bf16(acc[mt][nt], al[mt], bf[np][sb*2], bf[np][sb*2+1]);
                        }
                    }
                #pragma unroll
                for (int np = 0; np < 4; np++)
                    ldmx4(bf[np], BlA + (brow + np * 16) * SA + kb + bqof);
                #pragma unroll
                for (int np = 0; np < 4; np++)
                    #pragma unroll
                    for (int sb = 0; sb < 2; sb++) {
                        const int nt = np * 2 + sb;
                        #pragma unroll
                        for (int mt = 0; mt < 2; mt++)
                            mma_bf16(acc[mt][nt], ah[mt], bf[np][sb*2], bf[np][sb*2+1]);
                    }
            }
        }
        // epilogue: + b1 -> g_h1
        #pragma unroll
        for (int mt = 0; mt < 2; mt++) {
            const int row0 = rb + rbw + mt * 16 + (lane >> 2);
            #pragma unroll
            for (int nt = 0; nt < 8; nt++) {
                const int col = ch * 64 + nt * 8 + (lane & 3) * 2;
                const float b0 = s_b1[col], b1v = s_b1[col + 1];
                float2 v0 = { acc[mt][nt][0] + b0, acc[mt][nt][1] + b1v };
                float2 v1 = { acc[mt][nt][2] + b0, acc[mt][nt][3] + b1v };
                *(float2*)(g_h1 + (size_t)row0 * H + col)       = v0;
                *(float2*)(g_h1 + (size_t)(row0 + 8) * H + col) = v1;
            }
        }
    }
}

// ================= Z GEMM: gather x, Z = x@Wz, c = x.wkbq ====================
__global__ void __launch_bounds__(512, 1) k_z_mma(const float* __restrict__ emb,
                                                  const int* __restrict__ idx) {
    extern __shared__ char dsraw[];
    __shared__ float s_wkbq[H];
    const uint32_t raw  = smem_u32(dsraw);
    const uint32_t base = (raw + 1023u) & ~1023u;
    char* dsm = dsraw + (base - raw);
    const int tid = threadIdx.x, warp = tid >> 5, lane = tid & 31;

    char* Ahp = dsm;
    char* Alp = dsm + ATILE2;
    char* Bhp = dsm + 2 * ATILE2;
    char* Blp = Bhp + BTILE;
    conv_B(g_weff, Bhp, Blp, tid, 512);
    if (tid < H) s_wkbq[tid] = g_wkbq[tid];
    __syncthreads();

    const uint32_t AhA = smem_u32(Ahp), AlA = smem_u32(Alp);
    const uint32_t BhA = smem_u32(Bhp), BlA = smem_u32(Blp);
    const int rbw = (warp & 7) * 32;
    const int ch  = warp >> 3;

    for (int tile = blockIdx.x; tile < N_ENT / 256; tile += gridDim.x) {
        const int rb = tile * 256;
        {
            const int r = tid >> 1, hf = tid & 1;
            const int e = __ldg(idx + rb + r);
            const float4* src = (const float4*)(emb + (size_t)e * H) + hf * 16;
            float4* xdst = (float4*)(g_x + (size_t)(rb + r) * H) + hf * 16;
            char* ah = Ahp + r * SA + hf * 128;
            char* al = Alp + r * SA + hf * 128;
            float cp = 0.0f;
            #pragma unroll
            for (int j = 0; j < 16; j++) {
                const float4 v = __ldg(src + j);
                uint32_t hi[2], lo[2];
                split4(v, hi, lo);
                *(uint32_t*)(ah + j * 8)     = hi[0];
                *(uint32_t*)(ah + j * 8 + 4) = hi[1];
                *(uint32_t*)(al + j * 8)     = lo[0];
                *(uint32_t*)(al + j * 8 + 4) = lo[1];
                xdst[j] = v;
                const float* wb = s_wkbq + hf * 64 + j * 4;
                cp += v.x * wb[0] + v.y * wb[1] + v.z * wb[2] + v.w * wb[3];
            }
            cp += __shfl_xor_sync(0xffffffffu, cp, 1);
            if (hf == 0) g_c[rb + r] = cp;
        }
        __syncthreads();

        float acc[2][8][4];
        #pragma unroll
        for (int mt = 0; mt < 2; mt++)
            #pragma unroll
            for (int nt = 0; nt < 8; nt++)
                #pragma unroll
                for (int q = 0; q < 4; q++) acc[mt][nt][q] = 0.0f;

        MMA_TILE256(AhA, AlA, BhA, BlA, acc, rbw, ch, lane);

        #pragma unroll
        for (int mt = 0; mt < 2; mt++) {
            const int row0 = rb + rbw + mt * 16 + (lane >> 2);
            #pragma unroll
            for (int nt = 0; nt < 8; nt++) {
                const int col = ch * 64 + nt * 8 + (lane & 3) * 2;
                float2 v0 = { acc[mt][nt][0], acc[mt][nt][1] };
                float2 v1 = { acc[mt][nt][2], acc[mt][nt][3] };
                *(float2*)(g_z + (size_t)row0 * H + col)       = v0;
                *(float2*)(g_z + (size_t)(row0 + 8) * H + col) = v1;
            }
        }
        __syncthreads();
    }
}

// ================= attention aggregation (warp per dst) ======================
// xagg[d] = sum_e w_e x[src_e] / sum_e w_e, w_e = exp((x_d.Z_s + c_s)/sqrt(d))
__global__ void __launch_bounds__(256) k_attn(int t) {
    const int warp = threadIdx.x >> 5, lane = threadIdx.x & 31;
    const int d = blockIdx.x * 8 + warp;
    const float4 xd4 = ((const float4*)(g_x + (size_t)d * H))[lane];
    const int start = g_ptr[t][d], deg = g_deg[t][d];

    float den = 0.0f;
    float4 acc = {0.0f, 0.0f, 0.0f, 0.0f};
    for (int e = 0; e < deg; e++) {
        const int s = g_col[t][start + e];
        const float4 z4 = ((const float4*)(g_z + (size_t)s * H))[lane];
        const float4 x4 = ((const float4*)(g_x + (size_t)s * H))[lane];
        float dot = xd4.x * z4.x + xd4.y * z4.y + xd4.z * z4.z + xd4.w * z4.w;
        #pragma unroll
        for (int o = 16; o; o >>= 1) dot += __shfl_xor_sync(0xffffffffu, dot, o);
        const float w = expf((dot + __ldg(&g_c[s])) * INV_SQRT_D);
        den += w;
        acc.x += w * x4.x; acc.y += w * x4.y; acc.z += w * x4.z; acc.w += w * x4.w;
    }
    const float inv = (deg > 0) ? 1.0f / den : 0.0f;
    float4 o4 = { acc.x * inv, acc.y * inv, acc.z * inv, acc.w * inv };
    ((float4*)(g_xagg + (size_t)d * H))[lane] = o4;
}

// ================= GEMM2 + LN: h = LN(xagg@Wv + x@Ws + bv+bs)*g + b ==========
// 128-row tiles, 16 warps = 8m x 2ch, acc[8][4].
__global__ void __launch_bounds__(512, 1) k_gemm2ln(
    const float* __restrict__ Wv, const float* __restrict__ bv,
    const float* __restrict__ Ws, const float* __restrict__ bs,
    const float* __restrict__ lns, const float* __restrict__ lnb) {
    extern __shared__ char dsraw[];
    __shared__ float s_bias[H], s_g[H], s_b[H];
    __shared__ float sS1[H], sS2[H], sMu[H], sRstd[H];
    const uint32_t raw  = smem_u32(dsraw);
    const uint32_t base = (raw + 1023u) & ~1023u;
    char* dsm = dsraw + (base - raw);
    const int tid = threadIdx.x, warp = tid >> 5, lane = tid & 31;

    char* Ahp = dsm;
    char* Alp = dsm + ATILE;
    char* Bvh = dsm + 2 * ATILE;
    char* Bvl = Bvh + BTILE;
    char* Bsh = Bvl + BTILE;
    char* Bsl = Bsh + BTILE;
    conv_B(Wv, Bvh, Bvl, tid, 512);
    conv_B(Ws, Bsh, Bsl, tid, 512);
    if (tid < H) {
        s_bias[tid] = bv[tid] + bs[tid];
        s_g[tid] = lns[tid];
        s_b[tid] = lnb[tid];
    }
    __syncthreads();

    const uint32_t AhA = smem_u32(Ahp), AlA = smem_u32(Alp);
    const uint32_t BvhA = smem_u32(Bvh), BvlA = smem_u32(Bvl);
    const uint32_t BshA = smem_u32(Bsh), BslA = smem_u32(Bsl);
    const int m = warp >> 1, ch = warp & 1;
    const uint32_t arow = m * 16 + (lane & 15);
    const uint32_t aqof = (lane >> 4) * 16;
    const uint32_t brow = ch * 64 + ((lane >> 4) * 8) + (lane & 7);
    const uint32_t bqof = ((lane >> 3) & 1) * 16;

    for (int tile = blockIdx.x; tile < N_ENT / 128; tile += gridDim.x) {
        const int rb = tile * 128;
        float acc[8][4];
        #pragma unroll
        for (int nt = 0; nt < 8; nt++)
            #pragma unroll
            for (int q = 0; q < 4; q++) acc[nt][q] = 0.0f;

        #pragma unroll
        for (int phase = 0; phase < 2; phase++) {
            const float* A = phase ? g_x : g_xagg;
            const uint32_t BH = phase ? BshA : BvhA;
            const uint32_t BL = phase ? BslA : BvlA;
            {   // gather (sequential)
                const int r = tid >> 2, cq = tid & 3;
                const float4* src = (const float4*)(A + (size_t)(rb + r) * H) + cq * 8;
                char* ah = Ahp + r * SA + cq * 64;
                char* al = Alp + r * SA + cq * 64;
                #pragma unroll
                for (int j = 0; j < 8; j++) {
                    uint32_t hi[2], lo[2];
                    split4(__ldg(src + j), hi, lo);
                    *(uint32_t*)(ah + j * 8)     = hi[0];
                    *(uint32_t*)(ah + j * 8 + 4) = hi[1];
                    *(uint32_t*)(al + j * 8)     = lo[0];
                    *(uint32_t*)(al + j * 8 + 4) = lo[1];
                }
                if (phase == 1 && tid < H) { sS1[tid] = 0.0f; sS2[tid] = 0.0f; }
            }
            __syncthreads();
            #pragma unroll
            for (int ks = 0; ks < 8; ks++) {
                const uint32_t kb = ks * 32;
                uint32_t ah[4], al[4], bf[4][4];
                const uint32_t ao = arow * SA + kb + aqof;
                ldmx4(ah, AhA + ao);
                ldmx4(al, AlA + ao);
                #pragma unroll
                for (int np = 0; np < 4; np++)
                    ldmx4(bf[np], BH + (brow + np * 16) * SA + kb + bqof);
                #pragma unroll
                for (int np = 0; np < 4; np++)
                    #pragma unroll
                    for (int sb = 0; sb < 2; sb++) {
                        const int nt = np * 2 + sb;
                        mma_bf16(acc[nt], ah, bf[np][sb*2], bf[np][sb*2+1]);
                        mma_bf16(acc[nt], al, bf[np][sb*2], bf[np][sb*2+1]);
                    }
                #pragma unroll
                for (int np = 0; np < 4; np++)
                    ldmx4(bf[np], BL + (brow + np * 16) * SA + kb + bqof);
                #pragma unroll
                for (int np = 0; np < 4; np++)
                    #pragma unroll
                    for (int sb = 0; sb < 2; sb++)
                        mma_bf16(acc[np * 2 + sb], ah, bf[np][sb*2], bf[np][sb*2+1]);
            }
            __syncthreads();   // protect A before next phase / next tile
        }

        // bias + LN stats
        const int r0 = m * 16 + (lane >> 2), r1 = r0 + 8;
        float s1a = 0, s2a = 0, s1b = 0, s2b = 0;
        #pragma unroll
        for (int nt = 0; nt < 8; nt++) {
            const int col = ch * 64 + nt * 8 + (lane & 3) * 2;
            acc[nt][0] += s_bias[col]; acc[nt][1] += s_bias[col + 1];
            acc[nt][2] += s_bias[col]; acc[nt][3] += s_bias[col + 1];
            s1a += acc[nt][0] + acc[nt][1];
            s2a += acc[nt][0] * acc[nt][0] + acc[nt][1] * acc[nt][1];
            s1b += acc[nt][2] + acc[nt][3];
            s2b += acc[nt][2] * acc[nt][2] + acc[nt][3] * acc[nt][3];
        }
        #pragma unroll
        for (int o = 1; o < 4; o <<= 1) {
            s1a += __shfl_xor_sync(0xffffffffu, s1a, o);
            s2a += __shfl_xor_sync(0xffffffffu, s2a, o);
            s1b += __shfl_xor_sync(0xffffffffu, s1b, o);
            s2b += __shfl_xor_sync(0xffffffffu, s2b, o);
        }
        if ((lane & 3) == 0) {
            atomicAdd(&sS1[r0], s1a); atomicAdd(&sS2[r0], s2a);
            atomicAdd(&sS1[r1], s1b); atomicAdd(&sS2[r1], s2b);
        }
        __syncthreads();
        if (tid < H) {
            const float mu = sS1[tid] * (1.0f / H);
            const float var = sS2[tid] * (1.0f / H) - mu * mu;
            sMu[tid] = mu;
            sRstd[tid] = rsqrtf(var + LN_EPS);
        }
        __syncthreads();

        const float mu0 = sMu[r0], rs0 = sRstd[r0];
        const float mu1 = sMu[r1], rs1 = sRstd[r1];
        #pragma unroll
        for (int nt = 0; nt < 8; nt++) {
            const int col = ch * 64 + nt * 8 + (lane & 3) * 2;
            const float g0 = s_g[col], g1 = s_g[col + 1];
            const float b0 = s_b[col], b1v = s_b[col + 1];
            float2 v0 = { (acc[nt][0] - mu0) * rs0 * g0 + b0,
                          (acc[nt][1] - mu0) * rs0 * g1 + b1v };
            float2 v1 = { (acc[nt][2] - mu1) * rs1 * g0 + b0,
                          (acc[nt][3] - mu1) * rs1 * g1 + b1v };
            *(float2*)(g_hr + (size_t)(rb + r0) * H + col) = v0;
            *(float2*)(g_hr + (size_t)(rb + r1) * H + col) = v1;
        }
        __syncthreads();   // stats/A reused next tile
    }
}

// ================= HMMA hw = h @ W1_t (256-row tiles) ========================
__global__ void __launch_bounds__(512, 1) k_hw_mma(const float* __restrict__ W1t) {
    extern __shared__ char dsraw[];
    const uint32_t raw  = smem_u32(dsraw);
    const uint32_t base = (raw + 1023u) & ~1023u;
    char* dsm = dsraw + (base - raw);
    const int tid = threadIdx.x, warp = tid >> 5, lane = tid & 31;

    char* Ahp = dsm;
    char* Alp = dsm + ATILE2;
    char* Bhp = dsm + 2 * ATILE2;
    char* Blp = Bhp + BTILE;
    conv_B(W1t, Bhp, Blp, tid, 512);
    __syncthreads();

    const uint32_t AhA = smem_u32(Ahp), AlA = smem_u32(Alp);
    const uint32_t BhA = smem_u32(Bhp), BlA = smem_u32(Blp);
    const int rbw = (warp & 7) * 32;
    const int ch  = warp >> 3;

    for (int tile = blockIdx.x; tile < N_ENT / 256; tile += gridDim.x) {
        const int rb = tile * 256;
        {
            const int r = tid >> 1, hf = tid & 1;
            const float4* src = (const float4*)(g_hr + (size_t)(rb + r) * H) + hf * 16;
            char* ah = Ahp + r * SA + hf * 128;
            char* al = Alp + r * SA + hf * 128;
            #pragma unroll
            for (int j = 0; j < 16; j++) {
                uint32_t hi[2], lo[2];
                split4(__ldg(src + j), hi, lo);
                *(uint32_t*)(ah + j * 8)     = hi[0];
                *(uint32_t*)(ah + j * 8 + 4) = hi[1];
                *(uint32_t*)(al + j * 8)     = lo[0];
                *(uint32_t*)(al + j * 8 + 4) = lo[1];
            }
        }
        __syncthreads();

        float acc[2][8][4];
        #pragma unroll
        for (int mt = 0; mt < 2; mt++)
            #pragma unroll
            for (int nt = 0; nt < 8; nt++)
                #pragma unroll
                for (int q = 0; q < 4; q++) acc[mt][nt][q] = 0.0f;

        MMA_TILE256(AhA, AlA, BhA, BlA, acc, rbw, ch, lane);

        #pragma unroll
        for (int mt = 0; mt < 2; mt++) {
            const int row0 = rb + rbw + mt * 16 + (lane >> 2);
            #pragma unroll
            for (int nt = 0; nt < 8; nt++) {
                const int col = ch * 64 + nt * 8 + (lane & 3) * 2;
                float2 v0 = { acc[mt][nt][0], acc[mt][nt][1] };
                float2 v1 = { acc[mt][nt][2], acc[mt][nt][3] };
                *(float2*)(g_hw + (size_t)row0 * H + col)       = v0;
                *(float2*)(g_hw + (size_t)(row0 + 8) * H + col) = v1;
            }
        }
        __syncthreads();
    }
}

// ================= h1[d] += sum_e hw[col[e]]  (warp per dst) =================
__global__ void __launch_bounds__(256) k_h1add(int t) {
    const int warp = threadIdx.x >> 5, lane = threadIdx.x & 31;
    const int d = blockIdx.x * 8 + warp;
    const int start = g_ptr[t][d], deg = g_deg[t][d];
    if (deg == 0) return;
    float4 acc = {0.0f, 0.0f, 0.0f, 0.0f};
    for (int e = 0; e < deg; e++) {
        const int s = g_col[t][start + e];
        const float4 w4 = ((const float4*)(g_hw + (size_t)s * H))[lane];
        acc.x += w4.x; acc.y += w4.y; acc.z += w4.z; acc.w += w4.w;
    }
    float4* p = (float4*)(g_h1 + (size_t)d * H) + lane;
    float4 cur = *p;
    cur.x += acc.x; cur.y += acc.y; cur.z += acc.z; cur.w += acc.w;
    *p = cur;
}

// ================= tail MLP: relu -> W2(64) relu -> W3(1) ====================
__global__ void k_mlp(const float* __restrict__ W2, const float* __restrict__ b2,
                      const float* __restrict__ W3, const float* __restrict__ b3,
                      float* __restrict__ out) {
    __shared__ float h1s[H];
    __shared__ float red[2];
    const int row = blockIdx.x, tid = threadIdx.x;   // 64 threads
    h1s[tid]      = fmaxf(g_h1[(size_t)row * H + tid],      0.0f);
    h1s[tid + 64] = fmaxf(g_h1[(size_t)row * H + tid + 64], 0.0f);
    __syncthreads();
    float acc = b2[tid];
    #pragma unroll 4
    for (int k = 0; k < H; k++) acc = fmaf(h1s[k], W2[k * 64 + tid], acc);
    float v = fmaxf(acc, 0.0f) * W3[tid];
    #pragma unroll
    for (int o = 16; o; o >>= 1) v += __shfl_xor_sync(0xffffffffu, v, o);
    if ((tid & 31) == 0) red[tid >> 5] = v;
    __syncthreads();
    if (tid == 0) out[row] = red[0] + red[1] + b3[0];
}

// ================= host launcher =============================================
extern "C" void kernel_launch(void* const* d_in, const int* in_sizes, int n_in,
                              void* d_out, int out_size) {
    const float* tx_x = (const float*)d_in[0];
    const float* emb  = (const float*)d_in[1];
    const int*   eidx = (const int*)  d_in[2];
    const int*   esrc = (const int*)  d_in[3];
    const int*   edst = (const int*)  d_in[4];
    const float* Wq = (const float*)d_in[5],  *bq = (const float*)d_in[6];
    const float* Wk = (const float*)d_in[7];
    const float* Wv = (const float*)d_in[9],  *bv = (const float*)d_in[10];
    const float* Ws = (const float*)d_in[11], *bs = (const float*)d_in[12];
    const float* lns = (const float*)d_in[13], *lnb = (const float*)d_in[14];
    const float* W1 = (const float*)d_in[15], *b1 = (const float*)d_in[16];
    const float* W2 = (const float*)d_in[17], *b2 = (const float*)d_in[18];
    const float* W3 = (const float*)d_in[19], *b3 = (const float*)d_in[20];
    float* out = (float*)d_out;

    const int SM256 = 2 * ATILE2 + 2 * BTILE + 1024;   // 209920
    const int SMG2  = 2 * ATILE  + 4 * BTILE + 1024;   // 209920
    cudaFuncSetAttribute(k_init_mma, cudaFuncAttributeMaxDynamicSharedMemorySize, SM256);
    cudaFuncSetAttribute(k_z_mma,    cudaFuncAttributeMaxDynamicSharedMemorySize, SM256);
    cudaFuncSetAttribute(k_gemm2ln,  cudaFuncAttributeMaxDynamicSharedMemorySize, SMG2);
    cudaFuncSetAttribute(k_hw_mma,   cudaFuncAttributeMaxDynamicSharedMemorySize, SM256);

    k_prep<<<128, 128>>>(Wq, Wk, bq);

    k_zero_deg<<<(T_TYPES * N_ENT + 255) / 256, 256>>>();
    k_count   <<<(T_TYPES * NE + 255) / 256, 256>>>(edst);
    k_scanA   <<<T_TYPES * 64, 256>>>();
    k_scanB   <<<T_TYPES, 64>>>();
    k_scanC   <<<T_TYPES * 64, 256>>>();
    k_fill    <<<(T_TYPES * NE + 255) / 256, 256>>>(esrc, edst);

    k_init_mma<<<148, 512, SM256>>>(tx_x, W1, b1);

    for (int t = 0; t < T_TYPES; t++) {
        k_z_mma  <<<148, 512, SM256>>>(emb + (size_t)t * N_ENT * H,
                                       eidx + (size_t)t * N_ENT);
        k_attn   <<<N_ENT / 8, 256>>>(t);
        k_gemm2ln<<<148, 512, SMG2>>>(Wv, bv, Ws, bs, lns + t * H, lnb + t * H);
        k_hw_mma <<<148, 512, SM256>>>(W1 + (size_t)(TXF + t * H) * H);
        k_h1add  <<<NUM_TX / 8, 256>>>(t);
    }

    k_mlp<<<NUM_TX, 64>>>(W2, b2, W3, b3, out);
}

// round 6
// speedup vs baseline: 2.2455x; 1.0630x over previous
#include <cuda_runtime.h>
#include <cuda_bf16.h>
#include <math.h>
#include <stdint.h>

#define T_TYPES 11
#define NUM_TX  131072
#define N_ENT   131072
#define NE      262144
#define H       128
#define TXF     394
#define LN_EPS  1e-5f
#define INV_SQRT_D 0.08838834764831845f   // 1/sqrt(128)

// bf16 tile strides (bytes): 128 bf16 = 256B + 16B pad -> conflict-free ldmatrix
#define SA 272
#define ATILE   34816     // 128 rows * 272B
#define ATILE2  69632     // 256 rows * 272B
#define BTILE   34816     // 128 n-rows * 272B

// ---------------- scratch (device globals; no cudaMalloc allowed) ----------
__device__ uint32_t g_zb [(size_t)N_ENT * 64]; // x @ (Wk Wq^T), bf16x2 packed
__device__ float g_x   [(size_t)N_ENT * H];   // gathered embeddings
__device__ float g_xagg[(size_t)N_ENT * H];   // sum_e alpha x[src]
__device__ float g_hw  [(size_t)N_ENT * H];   // LN(h) @ W1_t
__device__ float g_h1  [(size_t)NUM_TX * H];  // layer-1 pre-activation accumulator
__device__ float g_c   [N_ENT];               // x_s . (Wk bq)
__device__ float g_weff[H * H];               // Wz[k][n]
__device__ float g_wkbq[H];

// CSR over dst, per type
__device__ int g_deg [T_TYPES][N_ENT];
__device__ int g_ptr [T_TYPES][N_ENT];
__device__ int g_cur [T_TYPES][N_ENT];
__device__ int g_col [T_TYPES][NE];
__device__ int g_bsum[T_TYPES][64];

// ================= helpers ===================================================
__device__ __forceinline__ uint32_t smem_u32(const void* p) {
    uint32_t a;
    asm("{ .reg .u64 t; cvta.to.shared.u64 t, %1; cvt.u32.u64 %0, t; }" : "=r"(a) : "l"(p));
    return a;
}
__device__ __forceinline__ void ldmx4(uint32_t* r, uint32_t addr) {
    asm volatile("ldmatrix.sync.aligned.m8n8.x4.shared.b16 {%0,%1,%2,%3}, [%4];"
        : "=r"(r[0]), "=r"(r[1]), "=r"(r[2]), "=r"(r[3]) : "r"(addr));
}
__device__ __forceinline__ void mma_bf16(float* c, const uint32_t* a, uint32_t b0, uint32_t b1) {
    asm volatile("mma.sync.aligned.m16n8k16.row.col.f32.bf16.bf16.f32 "
        "{%0,%1,%2,%3}, {%4,%5,%6,%7}, {%8,%9}, {%0,%1,%2,%3};"
        : "+f"(c[0]), "+f"(c[1]), "+f"(c[2]), "+f"(c[3])
        : "r"(a[0]), "r"(a[1]), "r"(a[2]), "r"(a[3]), "r"(b0), "r"(b1));
}
__device__ __forceinline__ uint32_t bfpack(float a, float b) {
    __nv_bfloat162 t = __floats2bfloat162_rn(a, b);
    return reinterpret_cast<uint32_t&>(t);
}
__device__ __forceinline__ void split4(float4 v, uint32_t* hi, uint32_t* lo) {
    __nv_bfloat16 hx = __float2bfloat16(v.x), hy = __float2bfloat16(v.y);
    __nv_bfloat16 hz = __float2bfloat16(v.z), hw = __float2bfloat16(v.w);
    __nv_bfloat162 h01; h01.x = hx; h01.y = hy;
    __nv_bfloat162 h23; h23.x = hz; h23.y = hw;
    hi[0] = reinterpret_cast<uint32_t&>(h01);
    hi[1] = reinterpret_cast<uint32_t&>(h23);
    lo[0] = bfpack(v.x - __bfloat162float(hx), v.y - __bfloat162float(hy));
    lo[1] = bfpack(v.z - __bfloat162float(hz), v.w - __bfloat162float(hw));
}
// split scalar pair into hi/lo bf16x2
__device__ __forceinline__ void split2(float a, float b, uint32_t& hi, uint32_t& lo) {
    __nv_bfloat16 ha = __float2bfloat16(a), hb = __float2bfloat16(b);
    __nv_bfloat162 hp; hp.x = ha; hp.y = hb;
    hi = reinterpret_cast<uint32_t&>(hp);
    lo = bfpack(a - __bfloat162float(ha), b - __bfloat162float(hb));
}

// convert fp32 weight (x@W layout) into split-bf16 B tiles: B[n][k] = W[k][n]
__device__ __forceinline__ void conv_B(const float* __restrict__ W, char* bh, char* bl,
                                       int tid, int nthr) {
    for (int i = tid; i < H * H; i += nthr) {
        const int k = i >> 7, n = i & 127;
        const float w = W[i];
        const __nv_bfloat16 h = __float2bfloat16(w);
        *(__nv_bfloat16*)(bh + n * SA + k * 2) = h;
        *(__nv_bfloat16*)(bl + n * SA + k * 2) = __float2bfloat16(w - __bfloat162float(h));
    }
}

// ================= prep: Wz = Wk Wq^T, wkbq = Wk bq ==========================
__global__ void k_prep(const float* __restrict__ Wq, const float* __restrict__ Wk,
                       const float* __restrict__ bq) {
    __shared__ float wkrow[H];
    const int b = blockIdx.x, a = threadIdx.x;
    wkrow[a] = Wk[b * H + a];
    __syncthreads();
    float s = 0.0f;
    #pragma unroll 4
    for (int j = 0; j < H; j++) s = fmaf(wkrow[j], Wq[a * H + j], s);
    g_weff[b * H + a] = s;           // Wz[k=b][n=a]
    if (b == 0) {
        float t = 0.0f;
        for (int j = 0; j < H; j++) t = fmaf(Wk[a * H + j], bq[j], t);
        g_wkbq[a] = t;
    }
}

// ================= CSR build =================================================
__global__ void k_zero_deg() {
    const int i = blockIdx.x * blockDim.x + threadIdx.x;
    if (i < T_TYPES * N_ENT) ((int*)g_deg)[i] = 0;
}
__global__ void k_count(const int* __restrict__ edst) {
    const int i = blockIdx.x * blockDim.x + threadIdx.x;
    if (i >= T_TYPES * NE) return;
    const int t = i / NE;
    atomicAdd(&g_deg[t][edst[i]], 1);
}
__global__ void k_scanA() {
    const int t = blockIdx.x >> 6, c = blockIdx.x & 63;
    const int base = c * 2048, tid = threadIdx.x;
    int v[8], s = 0;
    #pragma unroll
    for (int j = 0; j < 8; j++) { v[j] = g_deg[t][base + tid * 8 + j]; s += v[j]; }
    __shared__ int sm[256];
    sm[tid] = s; __syncthreads();
    for (int off = 1; off < 256; off <<= 1) {
        int x = (tid >= off) ? sm[tid - off] : 0;
        __syncthreads();
        sm[tid] += x;
        __syncthreads();
    }
    int run = (tid == 0) ? 0 : sm[tid - 1];
    if (tid == 255) g_bsum[t][c] = sm[255];
    #pragma unroll
    for (int j = 0; j < 8; j++) { g_ptr[t][base + tid * 8 + j] = run; run += v[j]; }
}
__global__ void k_scanB() {
    const int t = blockIdx.x, tid = threadIdx.x;
    __shared__ int sm[64];
    sm[tid] = g_bsum[t][tid]; __syncthreads();
    for (int off = 1; off < 64; off <<= 1) {
        int x = (tid >= off) ? sm[tid - off] : 0;
        __syncthreads();
        sm[tid] += x;
        __syncthreads();
    }
    g_bsum[t][tid] = (tid == 0) ? 0 : sm[tid - 1];
}
__global__ void k_scanC() {
    const int t = blockIdx.x >> 6, c = blockIdx.x & 63;
    const int base = c * 2048, tid = threadIdx.x;
    const int add = g_bsum[t][c];
    #pragma unroll
    for (int j = 0; j < 8; j++) {
        const int i = base + tid * 8 + j;
        const int p = g_ptr[t][i] + add;
        g_ptr[t][i] = p;
        g_cur[t][i] = p;
    }
}
__global__ void k_fill(const int* __restrict__ esrc, const int* __restrict__ edst) {
    const int i = blockIdx.x * blockDim.x + threadIdx.x;
    if (i >= T_TYPES * NE) return;
    const int t = i / NE;
    const int slot = atomicAdd(&g_cur[t][edst[i]], 1);
    g_col[t][slot] = esrc[i];
}

// ================= MMA core (256-row tile, acc[2][8][4], 16 warps) ==========
#define MMA_TILE256(AhA, AlA, BhA, BlA, acc, rbw, ch, lane)                          \
    {                                                                                 \
        const uint32_t arow = (rbw) + ((lane) & 15);                                  \
        const uint32_t aqof = ((lane) >> 4) * 16;                                     \
        const uint32_t brow = (ch) * 64 + (((lane) >> 4) * 8) + ((lane) & 7);         \
        const uint32_t bqof = (((lane) >> 3) & 1) * 16;                               \
        _Pragma("unroll")                                                             \
        for (int ks = 0; ks < 8; ks++) {                                              \
            const uint32_t kb = ks * 32;                                              \
            uint32_t ah[2][4], al[2][4], bf[4][4];                                    \
            _Pragma("unroll")                                                         \
            for (int mt = 0; mt < 2; mt++) {                                          \
                const uint32_t ao = (arow + mt * 16) * SA + kb + aqof;                \
                ldmx4(ah[mt], (AhA) + ao);                                            \
                ldmx4(al[mt], (AlA) + ao);                                            \
            }                                                                         \
            _Pragma("unroll")                                                         \
            for (int np = 0; np < 4; np++)                                            \
                ldmx4(bf[np], (BhA) + (brow + np * 16) * SA + kb + bqof);             \
            _Pragma("unroll")                                                         \
            for (int np = 0; np < 4; np++)                                            \
                _Pragma("unroll")                                                     \
                for (int sb = 0; sb < 2; sb++) {                                      \
                    const int nt = np * 2 + sb;                                       \
                    _Pragma("unroll")                                                 \
                    for (int mt = 0; mt < 2; mt++) {                                  \
                        mma_bf16(acc[mt][nt], ah[mt], bf[np][sb*2], bf[np][sb*2+1]);  \
                        mma_bf16(acc[mt][nt], al[mt], bf[np][sb*2], bf[np][sb*2+1]);  \
                    }                                                                 \
                }                                                                     \
            _Pragma("unroll")                                                         \
            for (int np = 0; np < 4; np++)                                            \
                ldmx4(bf[np], (BlA) + (brow + np * 16) * SA + kb + bqof);             \
            _Pragma("unroll")                                                         \
            for (int np = 0; np < 4; np++)                                            \
                _Pragma("unroll")                                                     \
                for (int sb = 0; sb < 2; sb++) {                                      \
                    const int nt = np * 2 + sb;                                       \
                    _Pragma("unroll")                                                 \
                    for (int mt = 0; mt < 2; mt++)                                    \
                        mma_bf16(acc[mt][nt], ah[mt], bf[np][sb*2], bf[np][sb*2+1]);  \
                }                                                                     \
        }                                                                             \
    }

// MMA core for 128-row tile: one m-slice per warp, acc[8][4]
#define MMA_TILE128(AhA, AlA, BH, BL, acc, m, ch, lane)                               \
    {                                                                                 \
        const uint32_t arow = (m) * 16 + ((lane) & 15);                               \
        const uint32_t aqof = ((lane) >> 4) * 16;                                     \
        const uint32_t brow = (ch) * 64 + (((lane) >> 4) * 8) + ((lane) & 7);         \
        const uint32_t bqof = (((lane) >> 3) & 1) * 16;                               \
        _Pragma("unroll")                                                             \
        for (int ks = 0; ks < 8; ks++) {                                              \
            const uint32_t kb = ks * 32;                                              \
            uint32_t ah[4], al[4], bf[4][4];                                          \
            const uint32_t ao = arow * SA + kb + aqof;                                \
            ldmx4(ah, (AhA) + ao);                                                    \
            ldmx4(al, (AlA) + ao);                                                    \
            _Pragma("unroll")                                                         \
            for (int np = 0; np < 4; np++)                                            \
                ldmx4(bf[np], (BH) + (brow + np * 16) * SA + kb + bqof);              \
            _Pragma("unroll")                                                         \
            for (int np = 0; np < 4; np++)                                            \
                _Pragma("unroll")                                                     \
                for (int sb = 0; sb < 2; sb++) {                                      \
                    const int nt = np * 2 + sb;                                       \
                    mma_bf16(acc[nt], ah, bf[np][sb*2], bf[np][sb*2+1]);              \
                    mma_bf16(acc[nt], al, bf[np][sb*2], bf[np][sb*2+1]);              \
                }                                                                     \
            _Pragma("unroll")                                                         \
            for (int np = 0; np < 4; np++)                                            \
                ldmx4(bf[np], (BL) + (brow + np * 16) * SA + kb + bqof);              \
            _Pragma("unroll")                                                         \
            for (int np = 0; np < 4; np++)                                            \
                _Pragma("unroll")                                                     \
                for (int sb = 0; sb < 2; sb++)                                        \
                    mma_bf16(acc[np * 2 + sb], ah, bf[np][sb*2], bf[np][sb*2+1]);     \
        }                                                                             \
    }

// ================= init_h1 via MMA: b1 + tx_x @ W1[0:394] ====================
__global__ void __launch_bounds__(512, 1) k_init_mma(const float* __restrict__ tx,
                                                     const float* __restrict__ W1,
                                                     const float* __restrict__ b1) {
    extern __shared__ char dsraw[];
    __shared__ float s_b1[H];
    const uint32_t raw  = smem_u32(dsraw);
    const uint32_t base = (raw + 1023u) & ~1023u;
    char* dsm = dsraw + (base - raw);
    const int tid = threadIdx.x, warp = tid >> 5, lane = tid & 31;

    char* Ahp = dsm;
    char* Alp = dsm + ATILE2;
    char* Bhp = dsm + 2 * ATILE2;
    char* Blp = Bhp + BTILE;
    const uint32_t AhA = smem_u32(Ahp), AlA = smem_u32(Alp);
    const uint32_t BhA = smem_u32(Bhp), BlA = smem_u32(Blp);

    if (tid < H) s_b1[tid] = b1[tid];

    const int rbw = (warp & 7) * 32;
    const int ch  = warp >> 3;

    for (int tile = blockIdx.x; tile < NUM_TX / 256; tile += gridDim.x) {
        const int rb = tile * 256;
        float acc[2][8][4];
        #pragma unroll
        for (int mt = 0; mt < 2; mt++)
            #pragma unroll
            for (int nt = 0; nt < 8; nt++)
                #pragma unroll
                for (int q = 0; q < 4; q++) acc[mt][nt][q] = 0.0f;

        for (int chunk = 0; chunk < 4; chunk++) {
            __syncthreads();
            const int kcols = (chunk < 3) ? 128 : 16;
            for (int i = tid; i < kcols * H; i += 512) {
                const int k = i >> 7, n = i & 127;
                const int kk = chunk * 128 + k;
                const float w = (kk < TXF) ? W1[(size_t)kk * H + n] : 0.0f;
                const __nv_bfloat16 h = __float2bfloat16(w);
                *(__nv_bfloat16*)(Bhp + n * SA + k * 2) = h;
                *(__nv_bfloat16*)(Blp + n * SA + k * 2) =
                    __float2bfloat16(w - __bfloat162float(h));
            }
            const int r = tid >> 1, hf = tid & 1;
            const float* rowp = tx + (size_t)(rb + r) * TXF;
            if (chunk < 3) {
                const float2* src = (const float2*)(rowp + chunk * 128 + hf * 64);
                char* ah = Ahp + r * SA + hf * 128;
                char* al = Alp + r * SA + hf * 128;
                #pragma unroll
                for (int j = 0; j < 16; j++) {
                    const float2 a = __ldg(src + j * 2);
                    const float2 b = __ldg(src + j * 2 + 1);
                    float4 v = { a.x, a.y, b.x, b.y };
                    uint32_t hi[2], lo[2];
                    split4(v, hi, lo);
                    *(uint32_t*)(ah + j * 8)     = hi[0];
                    *(uint32_t*)(ah + j * 8 + 4) = hi[1];
                    *(uint32_t*)(al + j * 8)     = lo[0];
                    *(uint32_t*)(al + j * 8 + 4) = lo[1];
                }
            } else {
                float vals[8];
                #pragma unroll
                for (int j = 0; j < 8; j++) {
                    const int c = 384 + hf * 8 + j;
                    vals[j] = (c < TXF) ? __ldg(rowp + c) : 0.0f;
                }
                char* ah = Ahp + r * SA + hf * 16;
                char* al = Alp + r * SA + hf * 16;
                #pragma unroll
                for (int p = 0; p < 4; p++) {
                    float4 v = { vals[p*2], vals[p*2+1], 0.0f, 0.0f };
                    uint32_t hi[2], lo[2];
                    split4(v, hi, lo);
                    *(uint32_t*)(ah + p * 4) = hi[0];
                    *(uint32_t*)(al + p * 4) = lo[0];
                }
            }
            __syncthreads();

            const uint32_t arow = rbw + (lane & 15);
            const uint32_t aqof = (lane >> 4) * 16;
            const uint32_t brow = ch * 64 + ((lane >> 4) * 8) + (lane & 7);
            const uint32_t bqof = ((lane >> 3) & 1) * 16;
            const int nks = (chunk < 3) ? 8 : 1;
            for (int ks = 0; ks < nks; ks++) {
                const uint32_t kb = ks * 32;
                uint32_t ah[2][4], al[2][4], bf[4][4];
                #pragma unroll
                for (int mt = 0; mt < 2; mt++) {
                    const uint32_t ao = (arow + mt * 16) * SA + kb + aqof;
                    ldmx4(ah[mt], AhA + ao);
                    ldmx4(al[mt], AlA + ao);
                }
                #pragma unroll
                for (int np = 0; np < 4; np++)
                    ldmx4(bf[np], BhA + (brow + np * 16) * SA + kb + bqof);
                #pragma unroll
                for (int np = 0; np < 4; np++)
                    #pragma unroll
                    for (int sb = 0; sb < 2; sb++) {
                        const int nt = np * 2 + sb;
                        #pragma unroll
                        for (int mt = 0; mt < 2; mt++) {
                            mma_bf16(acc[mt][nt], ah[mt], bf[np][sb*2], bf[np][sb*2+1]);
                            mma_bf16(acc[mt][nt], al[mt], bf[np][sb*2], bf[np][sb*2+1]);
                        }
                    }
                #pragma unroll
                for (int np = 0; np < 4; np++)
                    ldmx4(bf[np], BlA + (brow + np * 16) * SA + kb + bqof);
                #pragma unroll
                for (int np = 0; np < 4; np++)
                    #pragma unroll
                    for (int sb = 0; sb < 2; sb++) {
                        const int nt = np * 2 + sb;
                        #pragma unroll
                        for (int mt = 0; mt < 2; mt++)
                            mma_bf16(acc[mt][nt], ah[mt], bf[np][sb*2], bf[np][sb*2+1]);
                    }
            }
        }
        #pragma unroll
        for (int mt = 0; mt < 2; mt++) {
            const int row0 = rb + rbw + mt * 16 + (lane >> 2);
            #pragma unroll
            for (int nt = 0; nt < 8; nt++) {
                const int col = ch * 64 + nt * 8 + (lane & 3) * 2;
                const float b0 = s_b1[col], b1v = s_b1[col + 1];
                float2 v0 = { acc[mt][nt][0] + b0, acc[mt][nt][1] + b1v };
                float2 v1 = { acc[mt][nt][2] + b0, acc[mt][nt][3] + b1v };
                *(float2*)(g_h1 + (size_t)row0 * H + col)       = v0;
                *(float2*)(g_h1 + (size_t)(row0 + 8) * H + col) = v1;
            }
        }
    }
}

// ================= Z GEMM: gather x, Zb = bf16(x@Wz), c = x.wkbq =============
__global__ void __launch_bounds__(512, 1) k_z_mma(const float* __restrict__ emb,
                                                  const int* __restrict__ idx) {
    extern __shared__ char dsraw[];
    __shared__ float s_wkbq[H];
    const uint32_t raw  = smem_u32(dsraw);
    const uint32_t base = (raw + 1023u) & ~1023u;
    char* dsm = dsraw + (base - raw);
    const int tid = threadIdx.x, warp = tid >> 5, lane = tid & 31;

    char* Ahp = dsm;
    char* Alp = dsm + ATILE2;
    char* Bhp = dsm + 2 * ATILE2;
    char* Blp = Bhp + BTILE;
    conv_B(g_weff, Bhp, Blp, tid, 512);
    if (tid < H) s_wkbq[tid] = g_wkbq[tid];
    __syncthreads();

    const uint32_t AhA = smem_u32(Ahp), AlA = smem_u32(Alp);
    const uint32_t BhA = smem_u32(Bhp), BlA = smem_u32(Blp);
    const int rbw = (warp & 7) * 32;
    const int ch  = warp >> 3;

    for (int tile = blockIdx.x; tile < N_ENT / 256; tile += gridDim.x) {
        const int rb = tile * 256;
        {
            const int r = tid >> 1, hf = tid & 1;
            const int e = __ldg(idx + rb + r);
            const float4* src = (const float4*)(emb + (size_t)e * H) + hf * 16;
            float4* xdst = (float4*)(g_x + (size_t)(rb + r) * H) + hf * 16;
            char* ah = Ahp + r * SA + hf * 128;
            char* al = Alp + r * SA + hf * 128;
            float cp = 0.0f;
            #pragma unroll
            for (int j = 0; j < 16; j++) {
                const float4 v = __ldg(src + j);
                uint32_t hi[2], lo[2];
                split4(v, hi, lo);
                *(uint32_t*)(ah + j * 8)     = hi[0];
                *(uint32_t*)(ah + j * 8 + 4) = hi[1];
                *(uint32_t*)(al + j * 8)     = lo[0];
                *(uint32_t*)(al + j * 8 + 4) = lo[1];
                xdst[j] = v;
                const float* wb = s_wkbq + hf * 64 + j * 4;
                cp += v.x * wb[0] + v.y * wb[1] + v.z * wb[2] + v.w * wb[3];
            }
            cp += __shfl_xor_sync(0xffffffffu, cp, 1);
            if (hf == 0) g_c[rb + r] = cp;
        }
        __syncthreads();

        float acc[2][8][4];
        #pragma unroll
        for (int mt = 0; mt < 2; mt++)
            #pragma unroll
            for (int nt = 0; nt < 8; nt++)
                #pragma unroll
                for (int q = 0; q < 4; q++) acc[mt][nt][q] = 0.0f;

        MMA_TILE256(AhA, AlA, BhA, BlA, acc, rbw, ch, lane);

        #pragma unroll
        for (int mt = 0; mt < 2; mt++) {
            const int row0 = rb + rbw + mt * 16 + (lane >> 2);
            #pragma unroll
            for (int nt = 0; nt < 8; nt++) {
                const int col = ch * 64 + nt * 8 + (lane & 3) * 2;
                g_zb[(size_t)row0 * 64 + (col >> 1)] =
                    bfpack(acc[mt][nt][0], acc[mt][nt][1]);
                g_zb[(size_t)(row0 + 8) * 64 + (col >> 1)] =
                    bfpack(acc[mt][nt][2], acc[mt][nt][3]);
            }
        }
        __syncthreads();
    }
}

// ================= attention aggregation (warp per dst) ======================
// xagg[d] = sum_e w_e x[src_e] / sum_e w_e, w_e = exp((x_d.Z_s + c_s)/sqrt(d))
__global__ void __launch_bounds__(256) k_attn(int t) {
    const int warp = threadIdx.x >> 5, lane = threadIdx.x & 31;
    const int d = blockIdx.x * 8 + warp;
    const float4 xd4 = ((const float4*)(g_x + (size_t)d * H))[lane];
    const int start = g_ptr[t][d], deg = g_deg[t][d];

    float den = 0.0f;
    float4 acc = {0.0f, 0.0f, 0.0f, 0.0f};
    for (int e = 0; e < deg; e++) {
        const int s = g_col[t][start + e];
        const uint2 z2 = *((const uint2*)(g_zb + (size_t)s * 64) + lane);
        const float2 z0 = __bfloat1622float2(*(const __nv_bfloat162*)&z2.x);
        const float2 z1 = __bfloat1622float2(*(const __nv_bfloat162*)&z2.y);
        const float4 x4 = ((const float4*)(g_x + (size_t)s * H))[lane];
        float dot = xd4.x * z0.x + xd4.y * z0.y + xd4.z * z1.x + xd4.w * z1.y;
        #pragma unroll
        for (int o = 16; o; o >>= 1) dot += __shfl_xor_sync(0xffffffffu, dot, o);
        const float w = expf((dot + __ldg(&g_c[s])) * INV_SQRT_D);
        den += w;
        acc.x += w * x4.x; acc.y += w * x4.y; acc.z += w * x4.z; acc.w += w * x4.w;
    }
    const float inv = (deg > 0) ? 1.0f / den : 0.0f;
    float4 o4 = { acc.x * inv, acc.y * inv, acc.z * inv, acc.w * inv };
    ((float4*)(g_xagg + (size_t)d * H))[lane] = o4;
}

// ===== fused: h = LN(xagg@Wv + x@Ws + bv+bs)*g + b; hw = h @ W1_t ============
// 128-row tiles, 16 warps = 8m x 2ch. B1 (Ws) persistent; B0 cycles Wv -> W1t.
__global__ void __launch_bounds__(512, 1) k_fused(
    const float* __restrict__ Wv, const float* __restrict__ bv,
    const float* __restrict__ Ws, const float* __restrict__ bs,
    const float* __restrict__ lns, const float* __restrict__ lnb,
    const float* __restrict__ W1t) {
    extern __shared__ char dsraw[];
    __shared__ float s_bias[H], s_g[H], s_b[H];
    __shared__ float sS1[H], sS2[H], sMu[H], sRstd[H];
    const uint32_t raw  = smem_u32(dsraw);
    const uint32_t base = (raw + 1023u) & ~1023u;
    char* dsm = dsraw + (base - raw);
    const int tid = threadIdx.x, warp = tid >> 5, lane = tid & 31;

    char* Ahp = dsm;
    char* Alp = dsm + ATILE;
    char* B0h = dsm + 2 * ATILE;
    char* B0l = B0h + BTILE;
    char* B1h = B0l + BTILE;
    char* B1l = B1h + BTILE;
    conv_B(Ws, B1h, B1l, tid, 512);      // persistent
    if (tid < H) {
        s_bias[tid] = bv[tid] + bs[tid];
        s_g[tid] = lns[tid];
        s_b[tid] = lnb[tid];
    }

    const uint32_t AhA = smem_u32(Ahp), AlA = smem_u32(Alp);
    const uint32_t B0H = smem_u32(B0h), B0L = smem_u32(B0l);
    const uint32_t B1H = smem_u32(B1h), B1L = smem_u32(B1l);
    const int m = warp >> 1, ch = warp & 1;
    const int r0l = m * 16 + (lane >> 2), r1l = r0l + 8;   // local rows

    for (int tile = blockIdx.x; tile < N_ENT / 128; tile += gridDim.x) {
        const int rb = tile * 128;
        float acc[8][4];
        #pragma unroll
        for (int nt = 0; nt < 8; nt++)
            #pragma unroll
            for (int q = 0; q < 4; q++) acc[nt][q] = 0.0f;

        // ---- stage 1: B0 <- Wv, gather xagg, zero stats
        conv_B(Wv, B0h, B0l, tid, 512);
        {
            const int r = tid >> 2, cq = tid & 3;
            const float4* src = (const float4*)(g_xagg + (size_t)(rb + r) * H) + cq * 8;
            char* ah = Ahp + r * SA + cq * 64;
            char* al = Alp + r * SA + cq * 64;
            #pragma unroll
            for (int j = 0; j < 8; j++) {
                uint32_t hi[2], lo[2];
                split4(__ldg(src + j), hi, lo);
                *(uint32_t*)(ah + j * 8)     = hi[0];
                *(uint32_t*)(ah + j * 8 + 4) = hi[1];
                *(uint32_t*)(al + j * 8)     = lo[0];
                *(uint32_t*)(al + j * 8 + 4) = lo[1];
            }
        }
        if (tid < H) { sS1[tid] = 0.0f; sS2[tid] = 0.0f; }
        __syncthreads();
        MMA_TILE128(AhA, AlA, B0H, B0L, acc, m, ch, lane);
        __syncthreads();

        // ---- stage 2: gather x
        {
            const int r = tid >> 2, cq = tid & 3;
            const float4* src = (const float4*)(g_x + (size_t)(rb + r) * H) + cq * 8;
            char* ah = Ahp + r * SA + cq * 64;
            char* al = Alp + r * SA + cq * 64;
            #pragma unroll
            for (int j = 0; j < 8; j++) {
                uint32_t hi[2], lo[2];
                split4(__ldg(src + j), hi, lo);
                *(uint32_t*)(ah + j * 8)     = hi[0];
                *(uint32_t*)(ah + j * 8 + 4) = hi[1];
                *(uint32_t*)(al + j * 8)     = lo[0];
                *(uint32_t*)(al + j * 8 + 4) = lo[1];
            }
        }
        __syncthreads();
        MMA_TILE128(AhA, AlA, B1H, B1L, acc, m, ch, lane);

        // ---- bias + LN stats
        float s1a = 0, s2a = 0, s1b = 0, s2b = 0;
        #pragma unroll
        for (int nt = 0; nt < 8; nt++) {
            const int col = ch * 64 + nt * 8 + (lane & 3) * 2;
            acc[nt][0] += s_bias[col]; acc[nt][1] += s_bias[col + 1];
            acc[nt][2] += s_bias[col]; acc[nt][3] += s_bias[col + 1];
            s1a += acc[nt][0] + acc[nt][1];
            s2a += acc[nt][0] * acc[nt][0] + acc[nt][1] * acc[nt][1];
            s1b += acc[nt][2] + acc[nt][3];
            s2b += acc[nt][2] * acc[nt][2] + acc[nt][3] * acc[nt][3];
        }
        #pragma unroll
        for (int o = 1; o < 4; o <<= 1) {
            s1a += __shfl_xor_sync(0xffffffffu, s1a, o);
            s2a += __shfl_xor_sync(0xffffffffu, s2a, o);
            s1b += __shfl_xor_sync(0xffffffffu, s1b, o);
            s2b += __shfl_xor_sync(0xffffffffu, s2b, o);
        }
        if ((lane & 3) == 0) {
            atomicAdd(&sS1[r0l], s1a); atomicAdd(&sS2[r0l], s2a);
            atomicAdd(&sS1[r1l], s1b); atomicAdd(&sS2[r1l], s2b);
        }
        __syncthreads();
        if (tid < H) {
            const float mu = sS1[tid] * (1.0f / H);
            const float var = sS2[tid] * (1.0f / H) - mu * mu;
            sMu[tid] = mu;
            sRstd[tid] = rsqrtf(var + LN_EPS);
        }
        __syncthreads();

        // ---- stage 3: h -> A tile (split bf16), B0 <- W1t
        {
            const float mu0 = sMu[r0l], rs0 = sRstd[r0l];
            const float mu1 = sMu[r1l], rs1 = sRstd[r1l];
            #pragma unroll
            for (int nt = 0; nt < 8; nt++) {
                const int col = ch * 64 + nt * 8 + (lane & 3) * 2;
                const float g0 = s_g[col], g1 = s_g[col + 1];
                const float b0 = s_b[col], b1v = s_b[col + 1];
                const float h00 = (acc[nt][0] - mu0) * rs0 * g0 + b0;
                const float h01 = (acc[nt][1] - mu0) * rs0 * g1 + b1v;
                const float h10 = (acc[nt][2] - mu1) * rs1 * g0 + b0;
                const float h11 = (acc[nt][3] - mu1) * rs1 * g1 + b1v;
                uint32_t hi, lo;
                split2(h00, h01, hi, lo);
                *(uint32_t*)(Ahp + r0l * SA + col * 2) = hi;
                *(uint32_t*)(Alp + r0l * SA + col * 2) = lo;
                split2(h10, h11, hi, lo);
                *(uint32_t*)(Ahp + r1l * SA + col * 2) = hi;
                *(uint32_t*)(Alp + r1l * SA + col * 2) = lo;
            }
        }
        conv_B(W1t, B0h, B0l, tid, 512);
        __syncthreads();

        // ---- stage 3 GEMM: hw = h @ W1t
        #pragma unroll
        for (int nt = 0; nt < 8; nt++)
            #pragma unroll
            for (int q = 0; q < 4; q++) acc[nt][q] = 0.0f;
        MMA_TILE128(AhA, AlA, B0H, B0L, acc, m, ch, lane);

        #pragma unroll
        for (int nt = 0; nt < 8; nt++) {
            const int col = ch * 64 + nt * 8 + (lane & 3) * 2;
            float2 v0 = { acc[nt][0], acc[nt][1] };
            float2 v1 = { acc[nt][2], acc[nt][3] };
            *(float2*)(g_hw + (size_t)(rb + r0l) * H + col) = v0;
            *(float2*)(g_hw + (size_t)(rb + r1l) * H + col) = v1;
        }
        __syncthreads();
    }
}

// ================= h1[d] += sum_e hw[col[e]]  (warp per dst) =================
__global__ void __launch_bounds__(256) k_h1add(int t) {
    const int warp = threadIdx.x >> 5, lane = threadIdx.x & 31;
    const int d = blockIdx.x * 8 + warp;
    const int start = g_ptr[t][d], deg = g_deg[t][d];
    if (deg == 0) return;
    float4 acc = {0.0f, 0.0f, 0.0f, 0.0f};
    for (int e = 0; e < deg; e++) {
        const int s = g_col[t][start + e];
        const float4 w4 = ((const float4*)(g_hw + (size_t)s * H))[lane];
        acc.x += w4.x; acc.y += w4.y; acc.z += w4.z; acc.w += w4.w;
    }
    float4* p = (float4*)(g_h1 + (size_t)d * H) + lane;
    float4 cur = *p;
    cur.x += acc.x; cur.y += acc.y; cur.z += acc.z; cur.w += acc.w;
    *p = cur;
}

// ================= tail MLP: relu -> W2(64) relu -> W3(1) ====================
__global__ void k_mlp(const float* __restrict__ W2, const float* __restrict__ b2,
                      const float* __restrict__ W3, const float* __restrict__ b3,
                      float* __restrict__ out) {
    __shared__ float h1s[H];
    __shared__ float red[2];
    const int row = blockIdx.x, tid = threadIdx.x;   // 64 threads
    h1s[tid]      = fmaxf(g_h1[(size_t)row * H + tid],      0.0f);
    h1s[tid + 64] = fmaxf(g_h1[(size_t)row * H + tid + 64], 0.0f);
    __syncthreads();
    float acc = b2[tid];
    #pragma unroll 4
    for (int k = 0; k < H; k++) acc = fmaf(h1s[k], W2[k * 64 + tid], acc);
    float v = fmaxf(acc, 0.0f) * W3[tid];
    #pragma unroll
    for (int o = 16; o; o >>= 1) v += __shfl_xor_sync(0xffffffffu, v, o);
    if ((tid & 31) == 0) red[tid >> 5] = v;
    __syncthreads();
    if (tid == 0) out[row] = red[0] + red[1] + b3[0];
}

// ================= host launcher =============================================
extern "C" void kernel_launch(void* const* d_in, const int* in_sizes, int n_in,
                              void* d_out, int out_size) {
    const float* tx_x = (const float*)d_in[0];
    const float* emb  = (const float*)d_in[1];
    const int*   eidx = (const int*)  d_in[2];
    const int*   esrc = (const int*)  d_in[3];
    const int*   edst = (const int*)  d_in[4];
    const float* Wq = (const float*)d_in[5],  *bq = (const float*)d_in[6];
    const float* Wk = (const float*)d_in[7];
    const float* Wv = (const float*)d_in[9],  *bv = (const float*)d_in[10];
    const float* Ws = (const float*)d_in[11], *bs = (const float*)d_in[12];
    const float* lns = (const float*)d_in[13], *lnb = (const float*)d_in[14];
    const float* W1 = (const float*)d_in[15], *b1 = (const float*)d_in[16];
    const float* W2 = (const float*)d_in[17], *b2 = (const float*)d_in[18];
    const float* W3 = (const float*)d_in[19], *b3 = (const float*)d_in[20];
    float* out = (float*)d_out;

    const int SM256 = 2 * ATILE2 + 2 * BTILE + 1024;   // 209920
    const int SMF   = 2 * ATILE  + 4 * BTILE + 1024;   // 209920
    cudaFuncSetAttribute(k_init_mma, cudaFuncAttributeMaxDynamicSharedMemorySize, SM256);
    cudaFuncSetAttribute(k_z_mma,    cudaFuncAttributeMaxDynamicSharedMemorySize, SM256);
    cudaFuncSetAttribute(k_fused,    cudaFuncAttributeMaxDynamicSharedMemorySize, SMF);

    k_prep<<<128, 128>>>(Wq, Wk, bq);

    k_zero_deg<<<(T_TYPES * N_ENT + 255) / 256, 256>>>();
    k_count   <<<(T_TYPES * NE + 255) / 256, 256>>>(edst);
    k_scanA   <<<T_TYPES * 64, 256>>>();
    k_scanB   <<<T_TYPES, 64>>>();
    k_scanC   <<<T_TYPES * 64, 256>>>();
    k_fill    <<<(T_TYPES * NE + 255) / 256, 256>>>(esrc, edst);

    k_init_mma<<<148, 512, SM256>>>(tx_x, W1, b1);

    for (int t = 0; t < T_TYPES; t++) {
        k_z_mma <<<148, 512, SM256>>>(emb + (size_t)t * N_ENT * H,
                                      eidx + (size_t)t * N_ENT);
        k_attn  <<<N_ENT / 8, 256>>>(t);
        k_fused <<<148, 512, SMF>>>(Wv, bv, Ws, bs, lns + t * H, lnb + t * H,
                                    W1 + (size_t)(TXF + t * H) * H);
        k_h1add <<<NUM_TX / 8, 256>>>(t);
    }

    k_mlp<<<NUM_TX, 64>>>(W2, b2, W3, b3, out);
}